// round 12
// baseline (speedup 1.0000x reference)
#include <cuda_runtime.h>
#include <cuda_bf16.h>
#include <math.h>
#include <cstdint>

static constexpr int B_ = 2, S_ = 2048, E_ = 2048, H_ = 16, D_ = 128;
static constexpr int M_ = B_ * S_;   // 4096
static constexpr int N_ = E_;        // 2048
static constexpr int K_ = E_;        // 2048

// ---------------- scratch (__device__ globals: allocation-free rule) --------
__device__ __nv_bfloat16 g_qh[M_*K_], g_ql[M_*K_];
__device__ __nv_bfloat16 g_kh[M_*K_], g_kl[M_*K_];
__device__ __nv_bfloat16 g_vh[M_*K_], g_vl[M_*K_];
__device__ __nv_bfloat16 g_wqh[N_*K_], g_wql[N_*K_];
__device__ __nv_bfloat16 g_wkh[N_*K_], g_wkl[N_*K_];
__device__ __nv_bfloat16 g_wvh[N_*K_], g_wvl[N_*K_];
__device__ __nv_bfloat16 g_woh[N_*K_], g_wol[N_*K_];
// projections, head-split [B][H][S][D], hi/lo
__device__ __nv_bfloat16 g_Qh[B_*H_*S_*D_], g_Ql[B_*H_*S_*D_];
__device__ __nv_bfloat16 g_Kh[B_*H_*S_*D_], g_Kl[B_*H_*S_*D_];
__device__ __nv_bfloat16 g_Vh[B_*H_*S_*D_], g_Vl[B_*H_*S_*D_];
// attention output, [m][e] hi/lo
__device__ __nv_bfloat16 g_ch[M_*E_], g_cl[M_*E_];

// ---------------- helpers ---------------------------------------------------
__device__ __forceinline__ uint32_t smem_u32(const void* p) {
    uint32_t a;
    asm("{ .reg .u64 t; cvta.to.shared.u64 t, %1; cvt.u32.u64 %0, t; }" : "=r"(a) : "l"(p));
    return a;
}
__device__ __forceinline__ void ldmx4(uint32_t* r, uint32_t addr) {
    asm volatile("ldmatrix.sync.aligned.m8n8.x4.shared.b16 {%0,%1,%2,%3}, [%4];"
        : "=r"(r[0]), "=r"(r[1]), "=r"(r[2]), "=r"(r[3]) : "r"(addr));
}
__device__ __forceinline__ void ldmx4t(uint32_t* r, uint32_t addr) {
    asm volatile("ldmatrix.sync.aligned.m8n8.x4.trans.shared.b16 {%0,%1,%2,%3}, [%4];"
        : "=r"(r[0]), "=r"(r[1]), "=r"(r[2]), "=r"(r[3]) : "r"(addr));
}
__device__ __forceinline__ void mma16816(float* c, const uint32_t* a, uint32_t b0, uint32_t b1) {
    asm volatile("mma.sync.aligned.m16n8k16.row.col.f32.bf16.bf16.f32 "
        "{%0,%1,%2,%3}, {%4,%5,%6,%7}, {%8,%9}, {%0,%1,%2,%3};"
        : "+f"(c[0]), "+f"(c[1]), "+f"(c[2]), "+f"(c[3])
        : "r"(a[0]), "r"(a[1]), "r"(a[2]), "r"(a[3]), "r"(b0), "r"(b1));
}
__device__ __forceinline__ uint32_t pack_bf16x2(float lo, float hi) {
    uint32_t d;
    asm("cvt.rn.bf16x2.f32 %0, %1, %2;" : "=r"(d) : "f"(hi), "f"(lo));
    return d;
}
// fast exp2 on the FMA pipe (no MUFU). t <= 0 expected; clamped at -80.
__device__ __forceinline__ float fexp2(float t) {
    t = fmaxf(t, -80.0f);
    float r  = __fadd_rn(t, 12582912.0f);         // 1.5*2^23 magic round
    int   i  = __float_as_int(r) - 0x4B400000;
    float rf = __fadd_rn(r, -12582912.0f);
    float f  = __fadd_rn(t, -rf);                 // f in [-0.5, 0.5]
    float p  = 0.0013333558f;
    p = fmaf(p, f, 0.0096181291f);
    p = fmaf(p, f, 0.0555041087f);
    p = fmaf(p, f, 0.2402265069f);
    p = fmaf(p, f, 0.6931471806f);
    p = fmaf(p, f, 1.0f);
    return __int_as_float(__float_as_int(p) + (i << 23));
}

// ---------------- fp32 -> (hi, lo) bf16 splits (fused multi-tensor) ---------
__device__ __forceinline__ void split_one(const float* __restrict__ x,
    __nv_bfloat16* __restrict__ hi, __nv_bfloat16* __restrict__ lo, int i)
{
    float4 v = ((const float4*)x)[i];
    __nv_bfloat16 h0 = __float2bfloat16(v.x);
    __nv_bfloat16 h1 = __float2bfloat16(v.y);
    __nv_bfloat16 h2 = __float2bfloat16(v.z);
    __nv_bfloat16 h3 = __float2bfloat16(v.w);
    __nv_bfloat16 l0 = __float2bfloat16(v.x - __bfloat162float(h0));
    __nv_bfloat16 l1 = __float2bfloat16(v.y - __bfloat162float(h1));
    __nv_bfloat16 l2 = __float2bfloat16(v.z - __bfloat162float(h2));
    __nv_bfloat16 l3 = __float2bfloat16(v.w - __bfloat162float(h3));
    ((__nv_bfloat162*)hi)[i*2]   = __halves2bfloat162(h0, h1);
    ((__nv_bfloat162*)hi)[i*2+1] = __halves2bfloat162(h2, h3);
    ((__nv_bfloat162*)lo)[i*2]   = __halves2bfloat162(l0, l1);
    ((__nv_bfloat162*)lo)[i*2+1] = __halves2bfloat162(l2, l3);
}

__global__ __launch_bounds__(256)
void split3_kernel(const float* __restrict__ x0, __nv_bfloat16* h0, __nv_bfloat16* l0,
                   const float* __restrict__ x1, __nv_bfloat16* h1, __nv_bfloat16* l1,
                   const float* __restrict__ x2, __nv_bfloat16* h2, __nv_bfloat16* l2,
                   int n4)
{
    int i = blockIdx.x * 256 + threadIdx.x;
    if (i >= n4) return;
    int t = blockIdx.y;
    if (t == 0)      split_one(x0, h0, l0, i);
    else if (t == 1) split_one(x1, h1, l1, i);
    else             split_one(x2, h2, l2, i);
}

__global__ __launch_bounds__(256)
void split4_kernel(const float* __restrict__ x0, __nv_bfloat16* h0, __nv_bfloat16* l0,
                   const float* __restrict__ x1, __nv_bfloat16* h1, __nv_bfloat16* l1,
                   const float* __restrict__ x2, __nv_bfloat16* h2, __nv_bfloat16* l2,
                   const float* __restrict__ x3, __nv_bfloat16* h3, __nv_bfloat16* l3,
                   int n4)
{
    int i = blockIdx.x * 256 + threadIdx.x;
    if (i >= n4) return;
    int t = blockIdx.y;
    if (t == 0)      split_one(x0, h0, l0, i);
    else if (t == 1) split_one(x1, h1, l1, i);
    else if (t == 2) split_one(x2, h2, l2, i);
    else             split_one(x3, h3, l3, i);
}

// ---------------- HMMA GEMM: C = A @ W^T (3-pass bf16 split) ----------------
// 128x128 tile, BK=32, 128 threads (4 warps of 64x64), 4-stage cp.async.
// 3 CTAs/SM (launch_bounds regs<=168): latency hiding without extra smem traffic.
static constexpr int GEMM_SMEM = 4 * 16384;   // 65536

__global__ __launch_bounds__(128, 3)
void gemm_hmma(const __nv_bfloat16* __restrict__ Ah, const __nv_bfloat16* __restrict__ Al,
               const __nv_bfloat16* __restrict__ Wh, const __nv_bfloat16* __restrict__ Wl,
               float* __restrict__ Cf, __nv_bfloat16* __restrict__ Chi,
               __nv_bfloat16* __restrict__ Clo, int mode, float scale)
{
    extern __shared__ char sm[];
    const uint32_t sbase = smem_u32(sm);
    const int tid  = threadIdx.x;
    const int lane = tid & 31, wid = tid >> 5;
    const int wm = wid & 1, wn = wid >> 1;       // warp tile: rows 64*wm, cols 64*wn
    const int m0 = blockIdx.y * 128;
    const int n0 = blockIdx.x * 128;

    float acc[4][8][4];
#pragma unroll
    for (int i = 0; i < 4; i++)
#pragma unroll
        for (int j = 0; j < 8; j++)
#pragma unroll
            for (int t = 0; t < 4; t++) acc[i][j][t] = 0.f;

    const int crow = tid >> 2, cseg = tid & 3;

    const int NITER = 192;   // 3 passes x 64 k-iters of BK=32

#define G_ISSUE(it) do { \
        int pass_ = (it) >> 6; int kb_ = ((it) & 63) << 5; \
        const __nv_bfloat16* Ap_ = (pass_ == 2) ? Al : Ah; \
        const __nv_bfloat16* Wp_ = (pass_ == 1) ? Wl : Wh; \
        uint32_t st_ = sbase + (uint32_t)(((it) & 3) * 16384); \
        _Pragma("unroll") \
        for (int j_ = 0; j_ < 4; j_++) { \
            int row_ = crow + j_ * 32; \
            uint32_t off_ = (uint32_t)row_ * 64u + (uint32_t)((cseg ^ ((row_ >> 1) & 3)) << 4); \
            const void* ga_ = Ap_ + (size_t)(m0 + row_) * K_ + kb_ + cseg * 8; \
            const void* gb_ = Wp_ + (size_t)(n0 + row_) * K_ + kb_ + cseg * 8; \
            asm volatile("cp.async.cg.shared.global [%0], [%1], 16;" :: "r"(st_ + off_), "l"(ga_)); \
            asm volatile("cp.async.cg.shared.global [%0], [%1], 16;" :: "r"(st_ + 8192u + off_), "l"(gb_)); \
        } \
        asm volatile("cp.async.commit_group;"); \
    } while (0)

    G_ISSUE(0); G_ISSUE(1); G_ISSUE(2);

    const int rowA0 = wm * 64 + (lane & 7) + (lane & 8);
    const int asegb = (lane >> 4);
    const int rowB0 = wn * 64 + (lane & 7) + ((lane >> 4) << 3);
    const int bsegb = (lane >> 3) & 1;

    for (int it = 0; it < NITER; it++) {
        if (it < NITER - 2)      { asm volatile("cp.async.wait_group 2;" ::: "memory"); }
        else if (it == NITER - 2){ asm volatile("cp.async.wait_group 1;" ::: "memory"); }
        else                     { asm volatile("cp.async.wait_group 0;" ::: "memory"); }
        __syncthreads();
        if (it + 3 < NITER) G_ISSUE(it + 3);

        const uint32_t ab = sbase + (uint32_t)((it & 3) * 16384);
        const uint32_t bb = ab + 8192u;

#pragma unroll
        for (int ks = 0; ks < 2; ks++) {
            uint32_t a[4][4];
#pragma unroll
            for (int mt = 0; mt < 4; mt++) {
                int row = rowA0 + mt * 16;
                int sl = ks * 2 + asegb;
                ldmx4(a[mt], ab + (uint32_t)row * 64u + (uint32_t)((sl ^ ((row >> 1) & 3)) << 4));
            }
#pragma unroll
            for (int nb = 0; nb < 4; nb++) {
                int row = rowB0 + nb * 16;
                int sl = ks * 2 + bsegb;
                uint32_t b[4];
                ldmx4(b, bb + (uint32_t)row * 64u + (uint32_t)((sl ^ ((row >> 1) & 3)) << 4));
#pragma unroll
                for (int mt = 0; mt < 4; mt++) {
                    mma16816(acc[mt][2*nb],   a[mt], b[0], b[1]);
                    mma16816(acc[mt][2*nb+1], a[mt], b[2], b[3]);
                }
            }
        }
    }
#undef G_ISSUE

    // ---- epilogue ----
#pragma unroll
    for (int mt = 0; mt < 4; mt++) {
#pragma unroll
        for (int half = 0; half < 2; half++) {
            int m = m0 + wm * 64 + mt * 16 + (lane >> 2) + half * 8;
            if (mode == 1) {
                int b = m >> 11, s = m & (S_ - 1);
                int h = blockIdx.x;
                size_t base = (((size_t)(b * H_ + h)) * S_ + s) * (size_t)D_;
#pragma unroll
                for (int n8 = 0; n8 < 8; n8++) {
                    int c = wn * 64 + n8 * 8 + 2 * (lane & 3);
                    float v0 = acc[mt][n8][half*2]   * scale;
                    float v1 = acc[mt][n8][half*2+1] * scale;
                    __nv_bfloat16 h0 = __float2bfloat16(v0);
                    __nv_bfloat16 h1 = __float2bfloat16(v1);
                    __nv_bfloat16 l0 = __float2bfloat16(v0 - __bfloat162float(h0));
                    __nv_bfloat16 l1 = __float2bfloat16(v1 - __bfloat162float(h1));
                    *(__nv_bfloat162*)(Chi + base + c) = __halves2bfloat162(h0, h1);
                    *(__nv_bfloat162*)(Clo + base + c) = __halves2bfloat162(l0, l1);
                }
            } else {
#pragma unroll
                for (int n8 = 0; n8 < 8; n8++) {
                    int c = wn * 64 + n8 * 8 + 2 * (lane & 3);
                    float2 v;
                    v.x = acc[mt][n8][half*2];
                    v.y = acc[mt][n8][half*2+1];
                    *(float2*)(Cf + (size_t)m * N_ + n0 + c) = v;
                }
            }
        }
    }
}

// ---------------- HMMA flash attention --------------------------------------
// CTA: 256 threads (8 warps, 16 q-rows each), Br=128, Bc=64, D=128.
// Scores 3-pass hi/lo; P hi/lo; PV 3-pass. Accumulators interleaved at
// reuse distance 4 (tile pairs per fragment load).
static constexpr int AT_QH  = 0;
static constexpr int AT_QL  = 34816;
static constexpr int AT_KV0 = 69632;       // stage stride 69632
static constexpr int AT_KH = 0, AT_KL = 17408, AT_VH = 34816, AT_VL = 52224;
static constexpr int ATTN_SMEM = AT_KV0 + 2 * 69632;   // 208896

__device__ __forceinline__ void attn_issue_kv(
    uint32_t sb, int stage, int bh, int kv0, int tid,
    const __nv_bfloat16* Kh, const __nv_bfloat16* Kl,
    const __nv_bfloat16* Vh, const __nv_bfloat16* Vl)
{
    uint32_t kb = sb + AT_KV0 + (uint32_t)(stage * 69632);
    const __nv_bfloat16* srcs[4] = {Kh, Kl, Vh, Vl};
    const uint32_t offs[4] = {AT_KH, AT_KL, AT_VH, AT_VL};
#pragma unroll
    for (int m = 0; m < 4; m++) {
        const __nv_bfloat16* src = srcs[m] + ((size_t)bh * S_ + kv0) * D_;
#pragma unroll
        for (int j = 0; j < 4; j++) {
            int idx = tid + j * 256;
            int row = idx >> 4, seg = idx & 15;
            const void* g = src + (size_t)row * D_ + seg * 8;
            asm volatile("cp.async.cg.shared.global [%0], [%1], 16;"
                :: "r"(kb + offs[m] + (uint32_t)(row * 272 + seg * 16)), "l"(g));
        }
    }
    asm volatile("cp.async.commit_group;");
}

__global__ __launch_bounds__(256)
void attn_hmma(const __nv_bfloat16* __restrict__ Qh, const __nv_bfloat16* __restrict__ Ql,
               const __nv_bfloat16* __restrict__ Kh, const __nv_bfloat16* __restrict__ Kl,
               const __nv_bfloat16* __restrict__ Vh, const __nv_bfloat16* __restrict__ Vl,
               __nv_bfloat16* __restrict__ Chi, __nv_bfloat16* __restrict__ Clo)
{
    extern __shared__ char sm[];
    const uint32_t sb = smem_u32(sm);
    const int tid = threadIdx.x;
    const int lane = tid & 31, wid = tid >> 5;   // wid 0..7, rows 16*wid
    const int qt = (int)gridDim.x - 1 - (int)blockIdx.x;   // heavy tiles first
    const int bh = blockIdx.y;
    const int q0 = qt * 128;
    const int nt = 2 * qt + 2;

    // ---- load Q (hi+lo) as its own cp.async group ----
    {
        const __nv_bfloat16* qsrc[2] = {Qh + ((size_t)bh * S_ + q0) * D_,
                                        Ql + ((size_t)bh * S_ + q0) * D_};
        const uint32_t qoff[2] = {AT_QH, AT_QL};
#pragma unroll
        for (int m = 0; m < 2; m++) {
#pragma unroll
            for (int j = 0; j < 8; j++) {
                int idx = tid + j * 256;
                int row = idx >> 4, seg = idx & 15;
                const void* g = qsrc[m] + (size_t)row * D_ + seg * 8;
                asm volatile("cp.async.cg.shared.global [%0], [%1], 16;"
                    :: "r"(sb + qoff[m] + (uint32_t)(row * 272 + seg * 16)), "l"(g));
            }
        }
        asm volatile("cp.async.commit_group;");
    }
    attn_issue_kv(sb, 0, bh, 0, tid, Kh, Kl, Vh, Vl);
    if (nt > 1) attn_issue_kv(sb, 1, bh, 64, tid, Kh, Kl, Vh, Vl);

    float oacc[16][4];
#pragma unroll
    for (int n = 0; n < 16; n++)
#pragma unroll
        for (int t = 0; t < 4; t++) oacc[n][t] = 0.f;
    float mrow[2] = {-1e30f, -1e30f};
    float lrow[2] = {0.f, 0.f};

    for (int kt = 0; kt < nt; kt++) {
        const int kv0 = kt * 64;
        if (kt + 1 < nt) { asm volatile("cp.async.wait_group 1;" ::: "memory"); }
        else             { asm volatile("cp.async.wait_group 0;" ::: "memory"); }
        __syncthreads();
        const uint32_t kb = sb + AT_KV0 + (uint32_t)((kt & 1) * 69632);

        // ---- scores: S = Qh*Kh^T + Qh*Kl^T + Ql*Kh^T (pairs, dist-4) ----
        float sacc[8][4];
#pragma unroll
        for (int j = 0; j < 8; j++)
#pragma unroll
            for (int t = 0; t < 4; t++) sacc[j][t] = 0.f;

#pragma unroll
        for (int ks = 0; ks < 8; ks++) {
            uint32_t qa_h[4], qa_l[4];
            {
                int row = wid * 16 + (lane & 7) + (lane & 8);
                int seg = ks * 2 + (lane >> 4);
                ldmx4(qa_h, sb + AT_QH + (uint32_t)(row * 272 + seg * 16));
                ldmx4(qa_l, sb + AT_QL + (uint32_t)(row * 272 + seg * 16));
            }
#pragma unroll
            for (int nbp = 0; nbp < 2; nbp++) {
                int segk = ks * 2 + ((lane >> 3) & 1);
                int rowk0 = (2*nbp)   * 16 + (lane & 7) + ((lane >> 4) << 3);
                int rowk1 = (2*nbp+1) * 16 + (lane & 7) + ((lane >> 4) << 3);
                uint32_t kh0[4], kl0[4], kh1[4], kl1[4];
                ldmx4(kh0, kb + AT_KH + (uint32_t)(rowk0 * 272 + segk * 16));
                ldmx4(kh1, kb + AT_KH + (uint32_t)(rowk1 * 272 + segk * 16));
                ldmx4(kl0, kb + AT_KL + (uint32_t)(rowk0 * 272 + segk * 16));
                ldmx4(kl1, kb + AT_KL + (uint32_t)(rowk1 * 272 + segk * 16));
                float* s0 = sacc[4*nbp];     float* s1 = sacc[4*nbp+1];
                float* s2 = sacc[4*nbp+2];   float* s3 = sacc[4*nbp+3];
                mma16816(s0, qa_h, kh0[0], kh0[1]);
                mma16816(s1, qa_h, kh0[2], kh0[3]);
                mma16816(s2, qa_h, kh1[0], kh1[1]);
                mma16816(s3, qa_h, kh1[2], kh1[3]);
                mma16816(s0, qa_l, kh0[0], kh0[1]);
                mma16816(s1, qa_l, kh0[2], kh0[3]);
                mma16816(s2, qa_l, kh1[0], kh1[1]);
                mma16816(s3, qa_l, kh1[2], kh1[3]);
                mma16816(s0, qa_h, kl0[0], kl0[1]);
                mma16816(s1, qa_h, kl0[2], kl0[3]);
                mma16816(s2, qa_h, kl1[0], kl1[1]);
                mma16816(s3, qa_h, kl1[2], kl1[3]);
            }
        }

        // ---- causal mask (only last two tiles can cross the diagonal) ----
        if (kt >= nt - 2) {
#pragma unroll
            for (int j = 0; j < 8; j++)
#pragma unroll
                for (int e = 0; e < 4; e++) {
                    int col = kv0 + j * 8 + 2 * (lane & 3) + (e & 1);
                    int row = q0 + wid * 16 + (lane >> 2) + 8 * (e >> 1);
                    if (col > row) sacc[j][e] = -1e30f;
                }
        }

        // ---- online softmax (base-2; log2e folded into Q scale) ----
        float alph[2];
#pragma unroll
        for (int half = 0; half < 2; half++) {
            float mx = -1e30f;
#pragma unroll
            for (int j = 0; j < 8; j++)
                mx = fmaxf(mx, fmaxf(sacc[j][2*half], sacc[j][2*half+1]));
            mx = fmaxf(mx, __shfl_xor_sync(0xffffffffu, mx, 1));
            mx = fmaxf(mx, __shfl_xor_sync(0xffffffffu, mx, 2));
            float mo = mrow[half];
            float mn = fmaxf(mo, mx);
            float al = fexp2(mo - mn);
            float sum = 0.f;
#pragma unroll
            for (int j = 0; j < 8; j++) {
                float p0 = fexp2(sacc[j][2*half]   - mn);
                float p1 = fexp2(sacc[j][2*half+1] - mn);
                sacc[j][2*half] = p0; sacc[j][2*half+1] = p1;
                sum += p0 + p1;
            }
            sum += __shfl_xor_sync(0xffffffffu, sum, 1);
            sum += __shfl_xor_sync(0xffffffffu, sum, 2);
            mrow[half] = mn;
            lrow[half] = lrow[half] * al + sum;
            alph[half] = al;
        }
#pragma unroll
        for (int n = 0; n < 16; n++) {
            oacc[n][0] *= alph[0]; oacc[n][1] *= alph[0];
            oacc[n][2] *= alph[1]; oacc[n][3] *= alph[1];
        }

        // ---- PV: O += Ph*Vh + Pl*Vh + Ph*Vl (pairs, dist-4) ----
#pragma unroll
        for (int kk = 0; kk < 4; kk++) {
            uint32_t pah[4], pal[4];
#pragma unroll
            for (int r = 0; r < 4; r++) {
                int jj = 2*kk + (r >> 1);
                float a0 = sacc[jj][(r & 1) * 2 + 0];
                float a1 = sacc[jj][(r & 1) * 2 + 1];
                uint32_t hp = pack_bf16x2(a0, a1);
                union { uint32_t u; __nv_bfloat162 b; } cv; cv.u = hp;
                float h0f = __bfloat162float(cv.b.x);
                float h1f = __bfloat162float(cv.b.y);
                pah[r] = hp;
                pal[r] = pack_bf16x2(a0 - h0f, a1 - h1f);
            }
            int rowv = kk * 16 + ((lane >> 3) & 1) * 8 + (lane & 7);
            int colb = (lane >> 4) * 8;   // within 16-col group
#pragma unroll
            for (int nnp = 0; nnp < 4; nnp++) {
                uint32_t va0 = (uint32_t)(rowv * 272 + ((2*nnp)   * 16 + colb) * 2);
                uint32_t va1 = (uint32_t)(rowv * 272 + ((2*nnp+1) * 16 + colb) * 2);
                uint32_t vh0[4], vl0[4], vh1[4], vl1[4];
                ldmx4t(vh0, kb + AT_VH + va0);
                ldmx4t(vh1, kb + AT_VH + va1);
                ldmx4t(vl0, kb + AT_VL + va0);
                ldmx4t(vl1, kb + AT_VL + va1);
                float* o0 = oacc[4*nnp];     float* o1 = oacc[4*nnp+1];
                float* o2 = oacc[4*nnp+2];   float* o3 = oacc[4*nnp+3];
                mma16816(o0, pah, vh0[0], vh0[1]);
                mma16816(o1, pah, vh0[2], vh0[3]);
                mma16816(o2, pah, vh1[0], vh1[1]);
                mma16816(o3, pah, vh1[2], vh1[3]);
                mma16816(o0, pal, vh0[0], vh0[1]);
                mma16816(o1, pal, vh0[2], vh0[3]);
                mma16816(o2, pal, vh1[0], vh1[1]);
                mma16816(o3, pal, vh1[2], vh1[3]);
                mma16816(o0, pah, vl0[0], vl0[1]);
                mma16816(o1, pah, vl0[2], vl0[3]);
                mma16816(o2, pah, vl1[0], vl1[1]);
                mma16816(o3, pah, vl1[2], vl1[3]);
            }
        }

        __syncthreads();
        if (kt + 2 < nt) attn_issue_kv(sb, kt & 1, bh, (kt + 2) * 64, tid, Kh, Kl, Vh, Vl);
    }

    // ---- epilogue: ctx = O / l, write bf16 hi/lo at [b*S+s][h*D+d] ----
    const int b = bh >> 4, h = bh & 15;
#pragma unroll
    for (int half = 0; half < 2; half++) {
        float inv = 1.0f / lrow[half];
        int s = q0 + wid * 16 + (lane >> 2) + 8 * half;
        size_t base = ((size_t)b * S_ + s) * (size_t)E_ + h * D_;
#pragma unroll
        for (int nn = 0; nn < 16; nn++) {
            int c = nn * 8 + 2 * (lane & 3);
            float v0 = oacc[nn][2*half]   * inv;
            float v1 = oacc[nn][2*half+1] * inv;
            __nv_bfloat16 h0 = __float2bfloat16(v0);
            __nv_bfloat16 h1 = __float2bfloat16(v1);
            __nv_bfloat16 l0 = __float2bfloat16(v0 - __bfloat162float(h0));
            __nv_bfloat16 l1 = __float2bfloat16(v1 - __bfloat162float(h1));
            *(__nv_bfloat162*)(Chi + base + c) = __halves2bfloat162(h0, h1);
            *(__nv_bfloat162*)(Clo + base + c) = __halves2bfloat162(l0, l1);
        }
    }
}

// ---------------------------------------------------------------------------
extern "C" void kernel_launch(void* const* d_in, const int* in_sizes, int n_in,
                              void* d_out, int out_size)
{
    const float* q  = (const float*)d_in[0];
    const float* k  = (const float*)d_in[1];
    const float* v  = (const float*)d_in[2];
    const float* Wq = (const float*)d_in[4];
    const float* Wk = (const float*)d_in[5];
    const float* Wv = (const float*)d_in[6];
    const float* Wo = (const float*)d_in[7];
    float* out = (float*)d_out;

    __nv_bfloat16 *qh,*ql,*kh,*kl,*vh,*vl;
    __nv_bfloat16 *wqh,*wql,*wkh,*wkl,*wvh,*wvl,*woh,*wol;
    __nv_bfloat16 *Qph,*Qpl,*Kph,*Kpl,*Vph,*Vpl,*ch,*cl;
    cudaGetSymbolAddress((void**)&qh, g_qh);  cudaGetSymbolAddress((void**)&ql, g_ql);
    cudaGetSymbolAddress((void**)&kh, g_kh);  cudaGetSymbolAddress((void**)&kl, g_kl);
    cudaGetSymbolAddress((void**)&vh, g_vh);  cudaGetSymbolAddress((void**)&vl, g_vl);
    cudaGetSymbolAddress((void**)&wqh, g_wqh); cudaGetSymbolAddress((void**)&wql, g_wql);
    cudaGetSymbolAddress((void**)&wkh, g_wkh); cudaGetSymbolAddress((void**)&wkl, g_wkl);
    cudaGetSymbolAddress((void**)&wvh, g_wvh); cudaGetSymbolAddress((void**)&wvl, g_wvl);
    cudaGetSymbolAddress((void**)&woh, g_woh); cudaGetSymbolAddress((void**)&wol, g_wol);
    cudaGetSymbolAddress((void**)&Qph, g_Qh);  cudaGetSymbolAddress((void**)&Qpl, g_Ql);
    cudaGetSymbolAddress((void**)&Kph, g_Kh);  cudaGetSymbolAddress((void**)&Kpl, g_Kl);
    cudaGetSymbolAddress((void**)&Vph, g_Vh);  cudaGetSymbolAddress((void**)&Vpl, g_Vl);
    cudaGetSymbolAddress((void**)&ch, g_ch);   cudaGetSymbolAddress((void**)&cl, g_cl);

    cudaFuncSetAttribute(gemm_hmma, cudaFuncAttributeMaxDynamicSharedMemorySize, GEMM_SMEM);
    cudaFuncSetAttribute(attn_hmma, cudaFuncAttributeMaxDynamicSharedMemorySize, ATTN_SMEM);

    const int nx4 = M_ * K_ / 4;
    const int nw4 = N_ * K_ / 4;

    split3_kernel<<<dim3(nx4/256, 3), 256>>>(q, qh, ql, k, kh, kl, v, vh, vl, nx4);
    split4_kernel<<<dim3(nw4/256, 4), 256>>>(Wq, wqh, wql, Wk, wkh, wkl,
                                             Wv, wvh, wvl, Wo, woh, wol, nw4);

    // scale = log2(e)/sqrt(D): softmax computed base-2 is then exactly softmax(s)
    const float qscale = 0.12751744154070513f;
    dim3 gg(N_/128, M_/128);   // (16, 32)

    gemm_hmma<<<gg, 128, GEMM_SMEM>>>(qh, ql, wqh, wql, nullptr, Qph, Qpl, 1, qscale);
    gemm_hmma<<<gg, 128, GEMM_SMEM>>>(kh, kl, wkh, wkl, nullptr, Kph, Kpl, 1, 1.0f);
    gemm_hmma<<<gg, 128, GEMM_SMEM>>>(vh, vl, wvh, wvl, nullptr, Vph, Vpl, 1, 1.0f);

    attn_hmma<<<dim3(S_/128, B_*H_), 256, ATTN_SMEM>>>(Qph, Qpl, Kph, Kpl, Vph, Vpl, ch, cl);

    gemm_hmma<<<gg, 128, GEMM_SMEM>>>(ch, cl, woh, wol, out, nullptr, nullptr, 0, 1.0f);
}

// round 13
// speedup vs baseline: 1.1830x; 1.1830x over previous
#include <cuda_runtime.h>
#include <cuda_bf16.h>
#include <math.h>
#include <cstdint>

static constexpr int B_ = 2, S_ = 2048, E_ = 2048, H_ = 16, D_ = 128;
static constexpr int M_ = B_ * S_;   // 4096
static constexpr int N_ = E_;        // 2048
static constexpr int K_ = E_;        // 2048

// ---------------- scratch (__device__ globals: allocation-free rule) --------
__device__ __nv_bfloat16 g_qh[M_*K_], g_ql[M_*K_];
__device__ __nv_bfloat16 g_kh[M_*K_], g_kl[M_*K_];
__device__ __nv_bfloat16 g_vh[M_*K_], g_vl[M_*K_];
__device__ __nv_bfloat16 g_wqh[N_*K_], g_wql[N_*K_];
__device__ __nv_bfloat16 g_wkh[N_*K_], g_wkl[N_*K_];
__device__ __nv_bfloat16 g_wvh[N_*K_], g_wvl[N_*K_];
__device__ __nv_bfloat16 g_woh[N_*K_], g_wol[N_*K_];
// projections, head-split [B][H][S][D], hi/lo
__device__ __nv_bfloat16 g_Qh[B_*H_*S_*D_], g_Ql[B_*H_*S_*D_];
__device__ __nv_bfloat16 g_Kh[B_*H_*S_*D_], g_Kl[B_*H_*S_*D_];
__device__ __nv_bfloat16 g_Vh[B_*H_*S_*D_], g_Vl[B_*H_*S_*D_];
// attention output, [m][e] hi/lo
__device__ __nv_bfloat16 g_ch[M_*E_], g_cl[M_*E_];

// ---------------- helpers ---------------------------------------------------
__device__ __forceinline__ uint32_t smem_u32(const void* p) {
    uint32_t a;
    asm("{ .reg .u64 t; cvta.to.shared.u64 t, %1; cvt.u32.u64 %0, t; }" : "=r"(a) : "l"(p));
    return a;
}
__device__ __forceinline__ void ldmx4(uint32_t* r, uint32_t addr) {
    asm volatile("ldmatrix.sync.aligned.m8n8.x4.shared.b16 {%0,%1,%2,%3}, [%4];"
        : "=r"(r[0]), "=r"(r[1]), "=r"(r[2]), "=r"(r[3]) : "r"(addr));
}
__device__ __forceinline__ void ldmx4t(uint32_t* r, uint32_t addr) {
    asm volatile("ldmatrix.sync.aligned.m8n8.x4.trans.shared.b16 {%0,%1,%2,%3}, [%4];"
        : "=r"(r[0]), "=r"(r[1]), "=r"(r[2]), "=r"(r[3]) : "r"(addr));
}
__device__ __forceinline__ void mma16816(float* c, const uint32_t* a, uint32_t b0, uint32_t b1) {
    asm volatile("mma.sync.aligned.m16n8k16.row.col.f32.bf16.bf16.f32 "
        "{%0,%1,%2,%3}, {%4,%5,%6,%7}, {%8,%9}, {%0,%1,%2,%3};"
        : "+f"(c[0]), "+f"(c[1]), "+f"(c[2]), "+f"(c[3])
        : "r"(a[0]), "r"(a[1]), "r"(a[2]), "r"(a[3]), "r"(b0), "r"(b1));
}
__device__ __forceinline__ uint32_t pack_bf16x2(float lo, float hi) {
    uint32_t d;
    asm("cvt.rn.bf16x2.f32 %0, %1, %2;" : "=r"(d) : "f"(hi), "f"(lo));
    return d;
}
// fast exp2 on the FMA pipe (no MUFU). t <= 0 expected; clamped at -80.
__device__ __forceinline__ float fexp2(float t) {
    t = fmaxf(t, -80.0f);
    float r  = __fadd_rn(t, 12582912.0f);         // 1.5*2^23 magic round
    int   i  = __float_as_int(r) - 0x4B400000;
    float rf = __fadd_rn(r, -12582912.0f);
    float f  = __fadd_rn(t, -rf);                 // f in [-0.5, 0.5]
    float p  = 0.0013333558f;
    p = fmaf(p, f, 0.0096181291f);
    p = fmaf(p, f, 0.0555041087f);
    p = fmaf(p, f, 0.2402265069f);
    p = fmaf(p, f, 0.6931471806f);
    p = fmaf(p, f, 1.0f);
    return __int_as_float(__float_as_int(p) + (i << 23));
}

// ---------------- fp32 -> (hi, lo) bf16 splits (fused multi-tensor) ---------
__device__ __forceinline__ void split_one(const float* __restrict__ x,
    __nv_bfloat16* __restrict__ hi, __nv_bfloat16* __restrict__ lo, int i)
{
    float4 v = ((const float4*)x)[i];
    __nv_bfloat16 h0 = __float2bfloat16(v.x);
    __nv_bfloat16 h1 = __float2bfloat16(v.y);
    __nv_bfloat16 h2 = __float2bfloat16(v.z);
    __nv_bfloat16 h3 = __float2bfloat16(v.w);
    __nv_bfloat16 l0 = __float2bfloat16(v.x - __bfloat162float(h0));
    __nv_bfloat16 l1 = __float2bfloat16(v.y - __bfloat162float(h1));
    __nv_bfloat16 l2 = __float2bfloat16(v.z - __bfloat162float(h2));
    __nv_bfloat16 l3 = __float2bfloat16(v.w - __bfloat162float(h3));
    ((__nv_bfloat162*)hi)[i*2]   = __halves2bfloat162(h0, h1);
    ((__nv_bfloat162*)hi)[i*2+1] = __halves2bfloat162(h2, h3);
    ((__nv_bfloat162*)lo)[i*2]   = __halves2bfloat162(l0, l1);
    ((__nv_bfloat162*)lo)[i*2+1] = __halves2bfloat162(l2, l3);
}

__global__ __launch_bounds__(256)
void split3_kernel(const float* __restrict__ x0, __nv_bfloat16* h0, __nv_bfloat16* l0,
                   const float* __restrict__ x1, __nv_bfloat16* h1, __nv_bfloat16* l1,
                   const float* __restrict__ x2, __nv_bfloat16* h2, __nv_bfloat16* l2,
                   int n4)
{
    int i = blockIdx.x * 256 + threadIdx.x;
    if (i >= n4) return;
    int t = blockIdx.y;
    if (t == 0)      split_one(x0, h0, l0, i);
    else if (t == 1) split_one(x1, h1, l1, i);
    else             split_one(x2, h2, l2, i);
}

__global__ __launch_bounds__(256)
void split4_kernel(const float* __restrict__ x0, __nv_bfloat16* h0, __nv_bfloat16* l0,
                   const float* __restrict__ x1, __nv_bfloat16* h1, __nv_bfloat16* l1,
                   const float* __restrict__ x2, __nv_bfloat16* h2, __nv_bfloat16* l2,
                   const float* __restrict__ x3, __nv_bfloat16* h3, __nv_bfloat16* l3,
                   int n4)
{
    int i = blockIdx.x * 256 + threadIdx.x;
    if (i >= n4) return;
    int t = blockIdx.y;
    if (t == 0)      split_one(x0, h0, l0, i);
    else if (t == 1) split_one(x1, h1, l1, i);
    else if (t == 2) split_one(x2, h2, l2, i);
    else             split_one(x3, h3, l3, i);
}

// ---------------- HMMA GEMM: C = A @ W^T (3-pass bf16 split) ----------------
// R9 config (empirical local optimum): 128x128 tile, BK=32, 128 threads
// (4 warps of 64x64), 4-stage cp.async, launch_bounds(128,2).
static constexpr int GEMM_SMEM = 4 * 16384;   // 65536

__global__ __launch_bounds__(128, 2)
void gemm_hmma(const __nv_bfloat16* __restrict__ Ah, const __nv_bfloat16* __restrict__ Al,
               const __nv_bfloat16* __restrict__ Wh, const __nv_bfloat16* __restrict__ Wl,
               float* __restrict__ Cf, __nv_bfloat16* __restrict__ Chi,
               __nv_bfloat16* __restrict__ Clo, int mode, float scale)
{
    extern __shared__ char sm[];
    const uint32_t sbase = smem_u32(sm);
    const int tid  = threadIdx.x;
    const int lane = tid & 31, wid = tid >> 5;
    const int wm = wid & 1, wn = wid >> 1;       // warp tile: rows 64*wm, cols 64*wn
    const int m0 = blockIdx.y * 128;
    const int n0 = blockIdx.x * 128;

    float acc[4][8][4];
#pragma unroll
    for (int i = 0; i < 4; i++)
#pragma unroll
        for (int j = 0; j < 8; j++)
#pragma unroll
            for (int t = 0; t < 4; t++) acc[i][j][t] = 0.f;

    const int crow = tid >> 2, cseg = tid & 3;

    const int NITER = 192;   // 3 passes x 64 k-iters of BK=32

#define G_ISSUE(it) do { \
        int pass_ = (it) >> 6; int kb_ = ((it) & 63) << 5; \
        const __nv_bfloat16* Ap_ = (pass_ == 2) ? Al : Ah; \
        const __nv_bfloat16* Wp_ = (pass_ == 1) ? Wl : Wh; \
        uint32_t st_ = sbase + (uint32_t)(((it) & 3) * 16384); \
        _Pragma("unroll") \
        for (int j_ = 0; j_ < 4; j_++) { \
            int row_ = crow + j_ * 32; \
            uint32_t off_ = (uint32_t)row_ * 64u + (uint32_t)((cseg ^ ((row_ >> 1) & 3)) << 4); \
            const void* ga_ = Ap_ + (size_t)(m0 + row_) * K_ + kb_ + cseg * 8; \
            const void* gb_ = Wp_ + (size_t)(n0 + row_) * K_ + kb_ + cseg * 8; \
            asm volatile("cp.async.cg.shared.global [%0], [%1], 16;" :: "r"(st_ + off_), "l"(ga_)); \
            asm volatile("cp.async.cg.shared.global [%0], [%1], 16;" :: "r"(st_ + 8192u + off_), "l"(gb_)); \
        } \
        asm volatile("cp.async.commit_group;"); \
    } while (0)

    G_ISSUE(0); G_ISSUE(1); G_ISSUE(2);

    const int rowA0 = wm * 64 + (lane & 7) + (lane & 8);
    const int asegb = (lane >> 4);
    const int rowB0 = wn * 64 + (lane & 7) + ((lane >> 4) << 3);
    const int bsegb = (lane >> 3) & 1;

    for (int it = 0; it < NITER; it++) {
        if (it < NITER - 2)      { asm volatile("cp.async.wait_group 2;" ::: "memory"); }
        else if (it == NITER - 2){ asm volatile("cp.async.wait_group 1;" ::: "memory"); }
        else                     { asm volatile("cp.async.wait_group 0;" ::: "memory"); }
        __syncthreads();
        if (it + 3 < NITER) G_ISSUE(it + 3);

        const uint32_t ab = sbase + (uint32_t)((it & 3) * 16384);
        const uint32_t bb = ab + 8192u;

#pragma unroll
        for (int ks = 0; ks < 2; ks++) {
            uint32_t a[4][4];
#pragma unroll
            for (int mt = 0; mt < 4; mt++) {
                int row = rowA0 + mt * 16;
                int sl = ks * 2 + asegb;
                ldmx4(a[mt], ab + (uint32_t)row * 64u + (uint32_t)((sl ^ ((row >> 1) & 3)) << 4));
            }
#pragma unroll
            for (int nb = 0; nb < 4; nb++) {
                int row = rowB0 + nb * 16;
                int sl = ks * 2 + bsegb;
                uint32_t b[4];
                ldmx4(b, bb + (uint32_t)row * 64u + (uint32_t)((sl ^ ((row >> 1) & 3)) << 4));
#pragma unroll
                for (int mt = 0; mt < 4; mt++) {
                    mma16816(acc[mt][2*nb],   a[mt], b[0], b[1]);
                    mma16816(acc[mt][2*nb+1], a[mt], b[2], b[3]);
                }
            }
        }
    }
#undef G_ISSUE

    // ---- epilogue ----
#pragma unroll
    for (int mt = 0; mt < 4; mt++) {
#pragma unroll
        for (int half = 0; half < 2; half++) {
            int m = m0 + wm * 64 + mt * 16 + (lane >> 2) + half * 8;
            if (mode == 1) {
                int b = m >> 11, s = m & (S_ - 1);
                int h = blockIdx.x;
                size_t base = (((size_t)(b * H_ + h)) * S_ + s) * (size_t)D_;
#pragma unroll
                for (int n8 = 0; n8 < 8; n8++) {
                    int c = wn * 64 + n8 * 8 + 2 * (lane & 3);
                    float v0 = acc[mt][n8][half*2]   * scale;
                    float v1 = acc[mt][n8][half*2+1] * scale;
                    __nv_bfloat16 h0 = __float2bfloat16(v0);
                    __nv_bfloat16 h1 = __float2bfloat16(v1);
                    __nv_bfloat16 l0 = __float2bfloat16(v0 - __bfloat162float(h0));
                    __nv_bfloat16 l1 = __float2bfloat16(v1 - __bfloat162float(h1));
                    *(__nv_bfloat162*)(Chi + base + c) = __halves2bfloat162(h0, h1);
                    *(__nv_bfloat162*)(Clo + base + c) = __halves2bfloat162(l0, l1);
                }
            } else {
#pragma unroll
                for (int n8 = 0; n8 < 8; n8++) {
                    int c = wn * 64 + n8 * 8 + 2 * (lane & 3);
                    float2 v;
                    v.x = acc[mt][n8][half*2];
                    v.y = acc[mt][n8][half*2+1];
                    *(float2*)(Cf + (size_t)m * N_ + n0 + c) = v;
                }
            }
        }
    }
}

// ---------------- HMMA flash attention --------------------------------------
// CTA: 256 threads (8 warps, 16 q-rows each), Br=128, Bc=64, D=128.
// Scores 3-pass hi/lo; P hi/lo; PV 3-pass. Accumulators interleaved at
// reuse distance 4 (tile pairs per fragment load) — measured -38us vs dist-2.
static constexpr int AT_QH  = 0;
static constexpr int AT_QL  = 34816;
static constexpr int AT_KV0 = 69632;       // stage stride 69632
static constexpr int AT_KH = 0, AT_KL = 17408, AT_VH = 34816, AT_VL = 52224;
static constexpr int ATTN_SMEM = AT_KV0 + 2 * 69632;   // 208896

__device__ __forceinline__ void attn_issue_kv(
    uint32_t sb, int stage, int bh, int kv0, int tid,
    const __nv_bfloat16* Kh, const __nv_bfloat16* Kl,
    const __nv_bfloat16* Vh, const __nv_bfloat16* Vl)
{
    uint32_t kb = sb + AT_KV0 + (uint32_t)(stage * 69632);
    const __nv_bfloat16* srcs[4] = {Kh, Kl, Vh, Vl};
    const uint32_t offs[4] = {AT_KH, AT_KL, AT_VH, AT_VL};
#pragma unroll
    for (int m = 0; m < 4; m++) {
        const __nv_bfloat16* src = srcs[m] + ((size_t)bh * S_ + kv0) * D_;
#pragma unroll
        for (int j = 0; j < 4; j++) {
            int idx = tid + j * 256;
            int row = idx >> 4, seg = idx & 15;
            const void* g = src + (size_t)row * D_ + seg * 8;
            asm volatile("cp.async.cg.shared.global [%0], [%1], 16;"
                :: "r"(kb + offs[m] + (uint32_t)(row * 272 + seg * 16)), "l"(g));
        }
    }
    asm volatile("cp.async.commit_group;");
}

__global__ __launch_bounds__(256)
void attn_hmma(const __nv_bfloat16* __restrict__ Qh, const __nv_bfloat16* __restrict__ Ql,
               const __nv_bfloat16* __restrict__ Kh, const __nv_bfloat16* __restrict__ Kl,
               const __nv_bfloat16* __restrict__ Vh, const __nv_bfloat16* __restrict__ Vl,
               __nv_bfloat16* __restrict__ Chi, __nv_bfloat16* __restrict__ Clo)
{
    extern __shared__ char sm[];
    const uint32_t sb = smem_u32(sm);
    const int tid = threadIdx.x;
    const int lane = tid & 31, wid = tid >> 5;   // wid 0..7, rows 16*wid
    const int qt = (int)gridDim.x - 1 - (int)blockIdx.x;   // heavy tiles first
    const int bh = blockIdx.y;
    const int q0 = qt * 128;
    const int nt = 2 * qt + 2;

    // ---- load Q (hi+lo) as its own cp.async group ----
    {
        const __nv_bfloat16* qsrc[2] = {Qh + ((size_t)bh * S_ + q0) * D_,
                                        Ql + ((size_t)bh * S_ + q0) * D_};
        const uint32_t qoff[2] = {AT_QH, AT_QL};
#pragma unroll
        for (int m = 0; m < 2; m++) {
#pragma unroll
            for (int j = 0; j < 8; j++) {
                int idx = tid + j * 256;
                int row = idx >> 4, seg = idx & 15;
                const void* g = qsrc[m] + (size_t)row * D_ + seg * 8;
                asm volatile("cp.async.cg.shared.global [%0], [%1], 16;"
                    :: "r"(sb + qoff[m] + (uint32_t)(row * 272 + seg * 16)), "l"(g));
            }
        }
        asm volatile("cp.async.commit_group;");
    }
    attn_issue_kv(sb, 0, bh, 0, tid, Kh, Kl, Vh, Vl);
    if (nt > 1) attn_issue_kv(sb, 1, bh, 64, tid, Kh, Kl, Vh, Vl);

    float oacc[16][4];
#pragma unroll
    for (int n = 0; n < 16; n++)
#pragma unroll
        for (int t = 0; t < 4; t++) oacc[n][t] = 0.f;
    float mrow[2] = {-1e30f, -1e30f};
    float lrow[2] = {0.f, 0.f};

    for (int kt = 0; kt < nt; kt++) {
        const int kv0 = kt * 64;
        if (kt + 1 < nt) { asm volatile("cp.async.wait_group 1;" ::: "memory"); }
        else             { asm volatile("cp.async.wait_group 0;" ::: "memory"); }
        __syncthreads();
        const uint32_t kb = sb + AT_KV0 + (uint32_t)((kt & 1) * 69632);

        // ---- scores: S = Qh*Kh^T + Qh*Kl^T + Ql*Kh^T (pairs, dist-4) ----
        float sacc[8][4];
#pragma unroll
        for (int j = 0; j < 8; j++)
#pragma unroll
            for (int t = 0; t < 4; t++) sacc[j][t] = 0.f;

#pragma unroll
        for (int ks = 0; ks < 8; ks++) {
            uint32_t qa_h[4], qa_l[4];
            {
                int row = wid * 16 + (lane & 7) + (lane & 8);
                int seg = ks * 2 + (lane >> 4);
                ldmx4(qa_h, sb + AT_QH + (uint32_t)(row * 272 + seg * 16));
                ldmx4(qa_l, sb + AT_QL + (uint32_t)(row * 272 + seg * 16));
            }
#pragma unroll
            for (int nbp = 0; nbp < 2; nbp++) {
                int segk = ks * 2 + ((lane >> 3) & 1);
                int rowk0 = (2*nbp)   * 16 + (lane & 7) + ((lane >> 4) << 3);
                int rowk1 = (2*nbp+1) * 16 + (lane & 7) + ((lane >> 4) << 3);
                uint32_t kh0[4], kl0[4], kh1[4], kl1[4];
                ldmx4(kh0, kb + AT_KH + (uint32_t)(rowk0 * 272 + segk * 16));
                ldmx4(kh1, kb + AT_KH + (uint32_t)(rowk1 * 272 + segk * 16));
                ldmx4(kl0, kb + AT_KL + (uint32_t)(rowk0 * 272 + segk * 16));
                ldmx4(kl1, kb + AT_KL + (uint32_t)(rowk1 * 272 + segk * 16));
                float* s0 = sacc[4*nbp];     float* s1 = sacc[4*nbp+1];
                float* s2 = sacc[4*nbp+2];   float* s3 = sacc[4*nbp+3];
                mma16816(s0, qa_h, kh0[0], kh0[1]);
                mma16816(s1, qa_h, kh0[2], kh0[3]);
                mma16816(s2, qa_h, kh1[0], kh1[1]);
                mma16816(s3, qa_h, kh1[2], kh1[3]);
                mma16816(s0, qa_l, kh0[0], kh0[1]);
                mma16816(s1, qa_l, kh0[2], kh0[3]);
                mma16816(s2, qa_l, kh1[0], kh1[1]);
                mma16816(s3, qa_l, kh1[2], kh1[3]);
                mma16816(s0, qa_h, kl0[0], kl0[1]);
                mma16816(s1, qa_h, kl0[2], kl0[3]);
                mma16816(s2, qa_h, kl1[0], kl1[1]);
                mma16816(s3, qa_h, kl1[2], kl1[3]);
            }
        }

        // ---- causal mask (only last two tiles can cross the diagonal) ----
        if (kt >= nt - 2) {
#pragma unroll
            for (int j = 0; j < 8; j++)
#pragma unroll
                for (int e = 0; e < 4; e++) {
                    int col = kv0 + j * 8 + 2 * (lane & 3) + (e & 1);
                    int row = q0 + wid * 16 + (lane >> 2) + 8 * (e >> 1);
                    if (col > row) sacc[j][e] = -1e30f;
                }
        }

        // ---- online softmax (base-2; log2e folded into Q scale) ----
        float alph[2];
#pragma unroll
        for (int half = 0; half < 2; half++) {
            float mx = -1e30f;
#pragma unroll
            for (int j = 0; j < 8; j++)
                mx = fmaxf(mx, fmaxf(sacc[j][2*half], sacc[j][2*half+1]));
            mx = fmaxf(mx, __shfl_xor_sync(0xffffffffu, mx, 1));
            mx = fmaxf(mx, __shfl_xor_sync(0xffffffffu, mx, 2));
            float mo = mrow[half];
            float mn = fmaxf(mo, mx);
            float al = fexp2(mo - mn);
            float sum = 0.f;
#pragma unroll
            for (int j = 0; j < 8; j++) {
                float p0 = fexp2(sacc[j][2*half]   - mn);
                float p1 = fexp2(sacc[j][2*half+1] - mn);
                sacc[j][2*half] = p0; sacc[j][2*half+1] = p1;
                sum += p0 + p1;
            }
            sum += __shfl_xor_sync(0xffffffffu, sum, 1);
            sum += __shfl_xor_sync(0xffffffffu, sum, 2);
            mrow[half] = mn;
            lrow[half] = lrow[half] * al + sum;
            alph[half] = al;
        }
#pragma unroll
        for (int n = 0; n < 16; n++) {
            oacc[n][0] *= alph[0]; oacc[n][1] *= alph[0];
            oacc[n][2] *= alph[1]; oacc[n][3] *= alph[1];
        }

        // ---- PV: O += Ph*Vh + Pl*Vh + Ph*Vl (pairs, dist-4) ----
#pragma unroll
        for (int kk = 0; kk < 4; kk++) {
            uint32_t pah[4], pal[4];
#pragma unroll
            for (int r = 0; r < 4; r++) {
                int jj = 2*kk + (r >> 1);
                float a0 = sacc[jj][(r & 1) * 2 + 0];
                float a1 = sacc[jj][(r & 1) * 2 + 1];
                uint32_t hp = pack_bf16x2(a0, a1);
                union { uint32_t u; __nv_bfloat162 b; } cv; cv.u = hp;
                float h0f = __bfloat162float(cv.b.x);
                float h1f = __bfloat162float(cv.b.y);
                pah[r] = hp;
                pal[r] = pack_bf16x2(a0 - h0f, a1 - h1f);
            }
            int rowv = kk * 16 + ((lane >> 3) & 1) * 8 + (lane & 7);
            int colb = (lane >> 4) * 8;   // within 16-col group
#pragma unroll
            for (int nnp = 0; nnp < 4; nnp++) {
                uint32_t va0 = (uint32_t)(rowv * 272 + ((2*nnp)   * 16 + colb) * 2);
                uint32_t va1 = (uint32_t)(rowv * 272 + ((2*nnp+1) * 16 + colb) * 2);
                uint32_t vh0[4], vl0[4], vh1[4], vl1[4];
                ldmx4t(vh0, kb + AT_VH + va0);
                ldmx4t(vh1, kb + AT_VH + va1);
                ldmx4t(vl0, kb + AT_VL + va0);
                ldmx4t(vl1, kb + AT_VL + va1);
                float* o0 = oacc[4*nnp];     float* o1 = oacc[4*nnp+1];
                float* o2 = oacc[4*nnp+2];   float* o3 = oacc[4*nnp+3];
                mma16816(o0, pah, vh0[0], vh0[1]);
                mma16816(o1, pah, vh0[2], vh0[3]);
                mma16816(o2, pah, vh1[0], vh1[1]);
                mma16816(o3, pah, vh1[2], vh1[3]);
                mma16816(o0, pal, vh0[0], vh0[1]);
                mma16816(o1, pal, vh0[2], vh0[3]);
                mma16816(o2, pal, vh1[0], vh1[1]);
                mma16816(o3, pal, vh1[2], vh1[3]);
                mma16816(o0, pah, vl0[0], vl0[1]);
                mma16816(o1, pah, vl0[2], vl0[3]);
                mma16816(o2, pah, vl1[0], vl1[1]);
                mma16816(o3, pah, vl1[2], vl1[3]);
            }
        }

        __syncthreads();
        if (kt + 2 < nt) attn_issue_kv(sb, kt & 1, bh, (kt + 2) * 64, tid, Kh, Kl, Vh, Vl);
    }

    // ---- epilogue: ctx = O / l, write bf16 hi/lo at [b*S+s][h*D+d] ----
    const int b = bh >> 4, h = bh & 15;
#pragma unroll
    for (int half = 0; half < 2; half++) {
        float inv = 1.0f / lrow[half];
        int s = q0 + wid * 16 + (lane >> 2) + 8 * half;
        size_t base = ((size_t)b * S_ + s) * (size_t)E_ + h * D_;
#pragma unroll
        for (int nn = 0; nn < 16; nn++) {
            int c = nn * 8 + 2 * (lane & 3);
            float v0 = oacc[nn][2*half]   * inv;
            float v1 = oacc[nn][2*half+1] * inv;
            __nv_bfloat16 h0 = __float2bfloat16(v0);
            __nv_bfloat16 h1 = __float2bfloat16(v1);
            __nv_bfloat16 l0 = __float2bfloat16(v0 - __bfloat162float(h0));
            __nv_bfloat16 l1 = __float2bfloat16(v1 - __bfloat162float(h1));
            *(__nv_bfloat162*)(Chi + base + c) = __halves2bfloat162(h0, h1);
            *(__nv_bfloat162*)(Clo + base + c) = __halves2bfloat162(l0, l1);
        }
    }
}

// ---------------------------------------------------------------------------
extern "C" void kernel_launch(void* const* d_in, const int* in_sizes, int n_in,
                              void* d_out, int out_size)
{
    const float* q  = (const float*)d_in[0];
    const float* k  = (const float*)d_in[1];
    const float* v  = (const float*)d_in[2];
    const float* Wq = (const float*)d_in[4];
    const float* Wk = (const float*)d_in[5];
    const float* Wv = (const float*)d_in[6];
    const float* Wo = (const float*)d_in[7];
    float* out = (float*)d_out;

    __nv_bfloat16 *qh,*ql,*kh,*kl,*vh,*vl;
    __nv_bfloat16 *wqh,*wql,*wkh,*wkl,*wvh,*wvl,*woh,*wol;
    __nv_bfloat16 *Qph,*Qpl,*Kph,*Kpl,*Vph,*Vpl,*ch,*cl;
    cudaGetSymbolAddress((void**)&qh, g_qh);  cudaGetSymbolAddress((void**)&ql, g_ql);
    cudaGetSymbolAddress((void**)&kh, g_kh);  cudaGetSymbolAddress((void**)&kl, g_kl);
    cudaGetSymbolAddress((void**)&vh, g_vh);  cudaGetSymbolAddress((void**)&vl, g_vl);
    cudaGetSymbolAddress((void**)&wqh, g_wqh); cudaGetSymbolAddress((void**)&wql, g_wql);
    cudaGetSymbolAddress((void**)&wkh, g_wkh); cudaGetSymbolAddress((void**)&wkl, g_wkl);
    cudaGetSymbolAddress((void**)&wvh, g_wvh); cudaGetSymbolAddress((void**)&wvl, g_wvl);
    cudaGetSymbolAddress((void**)&woh, g_woh); cudaGetSymbolAddress((void**)&wol, g_wol);
    cudaGetSymbolAddress((void**)&Qph, g_Qh);  cudaGetSymbolAddress((void**)&Qpl, g_Ql);
    cudaGetSymbolAddress((void**)&Kph, g_Kh);  cudaGetSymbolAddress((void**)&Kpl, g_Kl);
    cudaGetSymbolAddress((void**)&Vph, g_Vh);  cudaGetSymbolAddress((void**)&Vpl, g_Vl);
    cudaGetSymbolAddress((void**)&ch, g_ch);   cudaGetSymbolAddress((void**)&cl, g_cl);

    cudaFuncSetAttribute(gemm_hmma, cudaFuncAttributeMaxDynamicSharedMemorySize, GEMM_SMEM);
    cudaFuncSetAttribute(attn_hmma, cudaFuncAttributeMaxDynamicSharedMemorySize, ATTN_SMEM);

    const int nx4 = M_ * K_ / 4;
    const int nw4 = N_ * K_ / 4;

    split3_kernel<<<dim3(nx4/256, 3), 256>>>(q, qh, ql, k, kh, kl, v, vh, vl, nx4);
    split4_kernel<<<dim3(nw4/256, 4), 256>>>(Wq, wqh, wql, Wk, wkh, wkl,
                                             Wv, wvh, wvl, Wo, woh, wol, nw4);

    // scale = log2(e)/sqrt(D): softmax computed base-2 is then exactly softmax(s)
    const float qscale = 0.12751744154070513f;
    dim3 gg(N_/128, M_/128);   // (16, 32)

    gemm_hmma<<<gg, 128, GEMM_SMEM>>>(qh, ql, wqh, wql, nullptr, Qph, Qpl, 1, qscale);
    gemm_hmma<<<gg, 128, GEMM_SMEM>>>(kh, kl, wkh, wkl, nullptr, Kph, Kpl, 1, 1.0f);
    gemm_hmma<<<gg, 128, GEMM_SMEM>>>(vh, vl, wvh, wvl, nullptr, Vph, Vpl, 1, 1.0f);

    attn_hmma<<<dim3(S_/128, B_*H_), 256, ATTN_SMEM>>>(Qph, Qpl, Kph, Kpl, Vph, Vpl, ch, cl);

    gemm_hmma<<<gg, 128, GEMM_SMEM>>>(ch, cl, woh, wol, out, nullptr, nullptr, 0, 1.0f);
}

// round 14
// speedup vs baseline: 1.2109x; 1.0236x over previous
#include <cuda_runtime.h>
#include <cuda_bf16.h>
#include <cuda_fp16.h>
#include <math.h>
#include <cstdint>

static constexpr int B_ = 2, S_ = 2048, E_ = 2048, H_ = 16, D_ = 128;
static constexpr int M_ = B_ * S_;   // 4096
static constexpr int N_ = E_;        // 2048
static constexpr int K_ = E_;        // 2048

// ---------------- scratch (__device__ globals: allocation-free rule) --------
__device__ __nv_bfloat16 g_qh[M_*K_], g_ql[M_*K_];
__device__ __nv_bfloat16 g_kh[M_*K_], g_kl[M_*K_];
__device__ __nv_bfloat16 g_vh[M_*K_], g_vl[M_*K_];
__device__ __nv_bfloat16 g_wqh[N_*K_], g_wql[N_*K_];
__device__ __nv_bfloat16 g_wkh[N_*K_], g_wkl[N_*K_];
__device__ __nv_bfloat16 g_wvh[N_*K_], g_wvl[N_*K_];
__device__ __nv_bfloat16 g_woh[N_*K_], g_wol[N_*K_];
// projections, head-split [B][H][S][D]
__device__ __nv_bfloat16 g_Qh[B_*H_*S_*D_], g_Ql[B_*H_*S_*D_];
__device__ __nv_bfloat16 g_Kh[B_*H_*S_*D_], g_Kl[B_*H_*S_*D_];
__device__ __half        g_Vf[B_*H_*S_*D_];          // V single fp16
// attention output, [m][e] hi/lo
__device__ __nv_bfloat16 g_ch[M_*E_], g_cl[M_*E_];

// ---------------- helpers ---------------------------------------------------
__device__ __forceinline__ uint32_t smem_u32(const void* p) {
    uint32_t a;
    asm("{ .reg .u64 t; cvta.to.shared.u64 t, %1; cvt.u32.u64 %0, t; }" : "=r"(a) : "l"(p));
    return a;
}
__device__ __forceinline__ void ldmx4(uint32_t* r, uint32_t addr) {
    asm volatile("ldmatrix.sync.aligned.m8n8.x4.shared.b16 {%0,%1,%2,%3}, [%4];"
        : "=r"(r[0]), "=r"(r[1]), "=r"(r[2]), "=r"(r[3]) : "r"(addr));
}
__device__ __forceinline__ void ldmx4t(uint32_t* r, uint32_t addr) {
    asm volatile("ldmatrix.sync.aligned.m8n8.x4.trans.shared.b16 {%0,%1,%2,%3}, [%4];"
        : "=r"(r[0]), "=r"(r[1]), "=r"(r[2]), "=r"(r[3]) : "r"(addr));
}
__device__ __forceinline__ void mma16816(float* c, const uint32_t* a, uint32_t b0, uint32_t b1) {
    asm volatile("mma.sync.aligned.m16n8k16.row.col.f32.bf16.bf16.f32 "
        "{%0,%1,%2,%3}, {%4,%5,%6,%7}, {%8,%9}, {%0,%1,%2,%3};"
        : "+f"(c[0]), "+f"(c[1]), "+f"(c[2]), "+f"(c[3])
        : "r"(a[0]), "r"(a[1]), "r"(a[2]), "r"(a[3]), "r"(b0), "r"(b1));
}
__device__ __forceinline__ void mma16816f(float* c, const uint32_t* a, uint32_t b0, uint32_t b1) {
    asm volatile("mma.sync.aligned.m16n8k16.row.col.f32.f16.f16.f32 "
        "{%0,%1,%2,%3}, {%4,%5,%6,%7}, {%8,%9}, {%0,%1,%2,%3};"
        : "+f"(c[0]), "+f"(c[1]), "+f"(c[2]), "+f"(c[3])
        : "r"(a[0]), "r"(a[1]), "r"(a[2]), "r"(a[3]), "r"(b0), "r"(b1));
}
__device__ __forceinline__ uint32_t pack_bf16x2(float lo, float hi) {
    uint32_t d;
    asm("cvt.rn.bf16x2.f32 %0, %1, %2;" : "=r"(d) : "f"(hi), "f"(lo));
    return d;
}
__device__ __forceinline__ uint32_t pack_f16x2(float lo, float hi) {
    uint32_t d;
    asm("cvt.rn.f16x2.f32 %0, %1, %2;" : "=r"(d) : "f"(hi), "f"(lo));
    return d;
}
// fast exp2 on the FMA pipe (no MUFU). t <= 0 expected; clamped at -80.
__device__ __forceinline__ float fexp2(float t) {
    t = fmaxf(t, -80.0f);
    float r  = __fadd_rn(t, 12582912.0f);         // 1.5*2^23 magic round
    int   i  = __float_as_int(r) - 0x4B400000;
    float rf = __fadd_rn(r, -12582912.0f);
    float f  = __fadd_rn(t, -rf);                 // f in [-0.5, 0.5]
    float p  = 0.0013333558f;
    p = fmaf(p, f, 0.0096181291f);
    p = fmaf(p, f, 0.0555041087f);
    p = fmaf(p, f, 0.2402265069f);
    p = fmaf(p, f, 0.6931471806f);
    p = fmaf(p, f, 1.0f);
    return __int_as_float(__float_as_int(p) + (i << 23));
}

// ---------------- fp32 -> (hi, lo) bf16 splits (fused multi-tensor) ---------
__device__ __forceinline__ void split_one(const float* __restrict__ x,
    __nv_bfloat16* __restrict__ hi, __nv_bfloat16* __restrict__ lo, int i)
{
    float4 v = ((const float4*)x)[i];
    __nv_bfloat16 h0 = __float2bfloat16(v.x);
    __nv_bfloat16 h1 = __float2bfloat16(v.y);
    __nv_bfloat16 h2 = __float2bfloat16(v.z);
    __nv_bfloat16 h3 = __float2bfloat16(v.w);
    __nv_bfloat16 l0 = __float2bfloat16(v.x - __bfloat162float(h0));
    __nv_bfloat16 l1 = __float2bfloat16(v.y - __bfloat162float(h1));
    __nv_bfloat16 l2 = __float2bfloat16(v.z - __bfloat162float(h2));
    __nv_bfloat16 l3 = __float2bfloat16(v.w - __bfloat162float(h3));
    ((__nv_bfloat162*)hi)[i*2]   = __halves2bfloat162(h0, h1);
    ((__nv_bfloat162*)hi)[i*2+1] = __halves2bfloat162(h2, h3);
    ((__nv_bfloat162*)lo)[i*2]   = __halves2bfloat162(l0, l1);
    ((__nv_bfloat162*)lo)[i*2+1] = __halves2bfloat162(l2, l3);
}

__global__ __launch_bounds__(256)
void split3_kernel(const float* __restrict__ x0, __nv_bfloat16* h0, __nv_bfloat16* l0,
                   const float* __restrict__ x1, __nv_bfloat16* h1, __nv_bfloat16* l1,
                   const float* __restrict__ x2, __nv_bfloat16* h2, __nv_bfloat16* l2,
                   int n4)
{
    int i = blockIdx.x * 256 + threadIdx.x;
    if (i >= n4) return;
    int t = blockIdx.y;
    if (t == 0)      split_one(x0, h0, l0, i);
    else if (t == 1) split_one(x1, h1, l1, i);
    else             split_one(x2, h2, l2, i);
}

__global__ __launch_bounds__(256)
void split4_kernel(const float* __restrict__ x0, __nv_bfloat16* h0, __nv_bfloat16* l0,
                   const float* __restrict__ x1, __nv_bfloat16* h1, __nv_bfloat16* l1,
                   const float* __restrict__ x2, __nv_bfloat16* h2, __nv_bfloat16* l2,
                   const float* __restrict__ x3, __nv_bfloat16* h3, __nv_bfloat16* l3,
                   int n4)
{
    int i = blockIdx.x * 256 + threadIdx.x;
    if (i >= n4) return;
    int t = blockIdx.y;
    if (t == 0)      split_one(x0, h0, l0, i);
    else if (t == 1) split_one(x1, h1, l1, i);
    else if (t == 2) split_one(x2, h2, l2, i);
    else             split_one(x3, h3, l3, i);
}

// ---------------- HMMA GEMM: C = A @ W^T (3-pass bf16 split) ----------------
// R9 config (empirical local optimum): 128x128 tile, BK=32, 128 threads
// (4 warps of 64x64), 4-stage cp.async, launch_bounds(128,2).
// mode: 0 = fp32 row-major; 1 = bf16 hi/lo head-split; 2 = fp16 single head-split.
static constexpr int GEMM_SMEM = 4 * 16384;   // 65536

__global__ __launch_bounds__(128, 2)
void gemm_hmma(const __nv_bfloat16* __restrict__ Ah, const __nv_bfloat16* __restrict__ Al,
               const __nv_bfloat16* __restrict__ Wh, const __nv_bfloat16* __restrict__ Wl,
               float* __restrict__ Cf, __nv_bfloat16* __restrict__ Chi,
               __nv_bfloat16* __restrict__ Clo, __half* __restrict__ Cf16,
               int mode, float scale)
{
    extern __shared__ char sm[];
    const uint32_t sbase = smem_u32(sm);
    const int tid  = threadIdx.x;
    const int lane = tid & 31, wid = tid >> 5;
    const int wm = wid & 1, wn = wid >> 1;       // warp tile: rows 64*wm, cols 64*wn
    const int m0 = blockIdx.y * 128;
    const int n0 = blockIdx.x * 128;

    float acc[4][8][4];
#pragma unroll
    for (int i = 0; i < 4; i++)
#pragma unroll
        for (int j = 0; j < 8; j++)
#pragma unroll
            for (int t = 0; t < 4; t++) acc[i][j][t] = 0.f;

    const int crow = tid >> 2, cseg = tid & 3;

    const int NITER = 192;   // 3 passes x 64 k-iters of BK=32

#define G_ISSUE(it) do { \
        int pass_ = (it) >> 6; int kb_ = ((it) & 63) << 5; \
        const __nv_bfloat16* Ap_ = (pass_ == 2) ? Al : Ah; \
        const __nv_bfloat16* Wp_ = (pass_ == 1) ? Wl : Wh; \
        uint32_t st_ = sbase + (uint32_t)(((it) & 3) * 16384); \
        _Pragma("unroll") \
        for (int j_ = 0; j_ < 4; j_++) { \
            int row_ = crow + j_ * 32; \
            uint32_t off_ = (uint32_t)row_ * 64u + (uint32_t)((cseg ^ ((row_ >> 1) & 3)) << 4); \
            const void* ga_ = Ap_ + (size_t)(m0 + row_) * K_ + kb_ + cseg * 8; \
            const void* gb_ = Wp_ + (size_t)(n0 + row_) * K_ + kb_ + cseg * 8; \
            asm volatile("cp.async.cg.shared.global [%0], [%1], 16;" :: "r"(st_ + off_), "l"(ga_)); \
            asm volatile("cp.async.cg.shared.global [%0], [%1], 16;" :: "r"(st_ + 8192u + off_), "l"(gb_)); \
        } \
        asm volatile("cp.async.commit_group;"); \
    } while (0)

    G_ISSUE(0); G_ISSUE(1); G_ISSUE(2);

    const int rowA0 = wm * 64 + (lane & 7) + (lane & 8);
    const int asegb = (lane >> 4);
    const int rowB0 = wn * 64 + (lane & 7) + ((lane >> 4) << 3);
    const int bsegb = (lane >> 3) & 1;

    for (int it = 0; it < NITER; it++) {
        if (it < NITER - 2)      { asm volatile("cp.async.wait_group 2;" ::: "memory"); }
        else if (it == NITER - 2){ asm volatile("cp.async.wait_group 1;" ::: "memory"); }
        else                     { asm volatile("cp.async.wait_group 0;" ::: "memory"); }
        __syncthreads();
        if (it + 3 < NITER) G_ISSUE(it + 3);

        const uint32_t ab = sbase + (uint32_t)((it & 3) * 16384);
        const uint32_t bb = ab + 8192u;

#pragma unroll
        for (int ks = 0; ks < 2; ks++) {
            uint32_t a[4][4];
#pragma unroll
            for (int mt = 0; mt < 4; mt++) {
                int row = rowA0 + mt * 16;
                int sl = ks * 2 + asegb;
                ldmx4(a[mt], ab + (uint32_t)row * 64u + (uint32_t)((sl ^ ((row >> 1) & 3)) << 4));
            }
#pragma unroll
            for (int nb = 0; nb < 4; nb++) {
                int row = rowB0 + nb * 16;
                int sl = ks * 2 + bsegb;
                uint32_t b[4];
                ldmx4(b, bb + (uint32_t)row * 64u + (uint32_t)((sl ^ ((row >> 1) & 3)) << 4));
#pragma unroll
                for (int mt = 0; mt < 4; mt++) {
                    mma16816(acc[mt][2*nb],   a[mt], b[0], b[1]);
                    mma16816(acc[mt][2*nb+1], a[mt], b[2], b[3]);
                }
            }
        }
    }
#undef G_ISSUE

    // ---- epilogue ----
#pragma unroll
    for (int mt = 0; mt < 4; mt++) {
#pragma unroll
        for (int half = 0; half < 2; half++) {
            int m = m0 + wm * 64 + mt * 16 + (lane >> 2) + half * 8;
            if (mode == 1) {
                int b = m >> 11, s = m & (S_ - 1);
                int h = blockIdx.x;
                size_t base = (((size_t)(b * H_ + h)) * S_ + s) * (size_t)D_;
#pragma unroll
                for (int n8 = 0; n8 < 8; n8++) {
                    int c = wn * 64 + n8 * 8 + 2 * (lane & 3);
                    float v0 = acc[mt][n8][half*2]   * scale;
                    float v1 = acc[mt][n8][half*2+1] * scale;
                    __nv_bfloat16 h0 = __float2bfloat16(v0);
                    __nv_bfloat16 h1 = __float2bfloat16(v1);
                    __nv_bfloat16 l0 = __float2bfloat16(v0 - __bfloat162float(h0));
                    __nv_bfloat16 l1 = __float2bfloat16(v1 - __bfloat162float(h1));
                    *(__nv_bfloat162*)(Chi + base + c) = __halves2bfloat162(h0, h1);
                    *(__nv_bfloat162*)(Clo + base + c) = __halves2bfloat162(l0, l1);
                }
            } else if (mode == 2) {
                int b = m >> 11, s = m & (S_ - 1);
                int h = blockIdx.x;
                size_t base = (((size_t)(b * H_ + h)) * S_ + s) * (size_t)D_;
#pragma unroll
                for (int n8 = 0; n8 < 8; n8++) {
                    int c = wn * 64 + n8 * 8 + 2 * (lane & 3);
                    __half2 hv = __floats2half2_rn(acc[mt][n8][half*2],
                                                   acc[mt][n8][half*2+1]);
                    *(__half2*)(Cf16 + base + c) = hv;
                }
            } else {
#pragma unroll
                for (int n8 = 0; n8 < 8; n8++) {
                    int c = wn * 64 + n8 * 8 + 2 * (lane & 3);
                    float2 v;
                    v.x = acc[mt][n8][half*2];
                    v.y = acc[mt][n8][half*2+1];
                    *(float2*)(Cf + (size_t)m * N_ + n0 + c) = v;
                }
            }
        }
    }
}

// ---------------- HMMA flash attention --------------------------------------
// CTA: 256 threads (8 warps, 16 q-rows each), Br=128, Bc=64, D=128.
// Scores 3-pass bf16 hi/lo; PV 2-pass fp16 (P hi/lo fp16 x single fp16 V).
static constexpr int AT_QH  = 0;
static constexpr int AT_QL  = 34816;
static constexpr int AT_KV0 = 69632;       // stage stride 52224
static constexpr int AT_KH = 0, AT_KL = 17408, AT_V = 34816;
static constexpr int KV_STRIDE = 52224;
static constexpr int ATTN_SMEM = AT_KV0 + 2 * KV_STRIDE;   // 174080

__device__ __forceinline__ void attn_issue_kv(
    uint32_t sb, int stage, int bh, int kv0, int tid,
    const __nv_bfloat16* Kh, const __nv_bfloat16* Kl, const __half* Vf)
{
    uint32_t kb = sb + AT_KV0 + (uint32_t)(stage * KV_STRIDE);
    const size_t ebase = ((size_t)bh * S_ + kv0) * D_;   // element offset (2B elems)
    const char* srcs[3] = {(const char*)(Kh + ebase), (const char*)(Kl + ebase),
                           (const char*)(Vf + ebase)};
    const uint32_t offs[3] = {AT_KH, AT_KL, AT_V};
#pragma unroll
    for (int m = 0; m < 3; m++) {
#pragma unroll
        for (int j = 0; j < 4; j++) {
            int idx = tid + j * 256;
            int row = idx >> 4, seg = idx & 15;
            const void* g = srcs[m] + (size_t)row * (D_ * 2) + seg * 16;
            asm volatile("cp.async.cg.shared.global [%0], [%1], 16;"
                :: "r"(kb + offs[m] + (uint32_t)(row * 272 + seg * 16)), "l"(g));
        }
    }
    asm volatile("cp.async.commit_group;");
}

__global__ __launch_bounds__(256)
void attn_hmma(const __nv_bfloat16* __restrict__ Qh, const __nv_bfloat16* __restrict__ Ql,
               const __nv_bfloat16* __restrict__ Kh, const __nv_bfloat16* __restrict__ Kl,
               const __half* __restrict__ Vf,
               __nv_bfloat16* __restrict__ Chi, __nv_bfloat16* __restrict__ Clo)
{
    extern __shared__ char sm[];
    const uint32_t sb = smem_u32(sm);
    const int tid = threadIdx.x;
    const int lane = tid & 31, wid = tid >> 5;   // wid 0..7, rows 16*wid
    const int qt = (int)gridDim.x - 1 - (int)blockIdx.x;   // heavy tiles first
    const int bh = blockIdx.y;
    const int q0 = qt * 128;
    const int nt = 2 * qt + 2;

    // ---- load Q (hi+lo) as its own cp.async group ----
    {
        const __nv_bfloat16* qsrc[2] = {Qh + ((size_t)bh * S_ + q0) * D_,
                                        Ql + ((size_t)bh * S_ + q0) * D_};
        const uint32_t qoff[2] = {AT_QH, AT_QL};
#pragma unroll
        for (int m = 0; m < 2; m++) {
#pragma unroll
            for (int j = 0; j < 8; j++) {
                int idx = tid + j * 256;
                int row = idx >> 4, seg = idx & 15;
                const void* g = qsrc[m] + (size_t)row * D_ + seg * 8;
                asm volatile("cp.async.cg.shared.global [%0], [%1], 16;"
                    :: "r"(sb + qoff[m] + (uint32_t)(row * 272 + seg * 16)), "l"(g));
            }
        }
        asm volatile("cp.async.commit_group;");
    }
    attn_issue_kv(sb, 0, bh, 0, tid, Kh, Kl, Vf);
    if (nt > 1) attn_issue_kv(sb, 1, bh, 64, tid, Kh, Kl, Vf);

    float oacc[16][4];
#pragma unroll
    for (int n = 0; n < 16; n++)
#pragma unroll
        for (int t = 0; t < 4; t++) oacc[n][t] = 0.f;
    float mrow[2] = {-1e30f, -1e30f};
    float lrow[2] = {0.f, 0.f};

    for (int kt = 0; kt < nt; kt++) {
        const int kv0 = kt * 64;
        if (kt + 1 < nt) { asm volatile("cp.async.wait_group 1;" ::: "memory"); }
        else             { asm volatile("cp.async.wait_group 0;" ::: "memory"); }
        __syncthreads();
        const uint32_t kb = sb + AT_KV0 + (uint32_t)((kt & 1) * KV_STRIDE);

        // ---- scores: S = Qh*Kh^T + Qh*Kl^T + Ql*Kh^T (pairs, dist-4) ----
        float sacc[8][4];
#pragma unroll
        for (int j = 0; j < 8; j++)
#pragma unroll
            for (int t = 0; t < 4; t++) sacc[j][t] = 0.f;

#pragma unroll
        for (int ks = 0; ks < 8; ks++) {
            uint32_t qa_h[4], qa_l[4];
            {
                int row = wid * 16 + (lane & 7) + (lane & 8);
                int seg = ks * 2 + (lane >> 4);
                ldmx4(qa_h, sb + AT_QH + (uint32_t)(row * 272 + seg * 16));
                ldmx4(qa_l, sb + AT_QL + (uint32_t)(row * 272 + seg * 16));
            }
#pragma unroll
            for (int nbp = 0; nbp < 2; nbp++) {
                int segk = ks * 2 + ((lane >> 3) & 1);
                int rowk0 = (2*nbp)   * 16 + (lane & 7) + ((lane >> 4) << 3);
                int rowk1 = (2*nbp+1) * 16 + (lane & 7) + ((lane >> 4) << 3);
                uint32_t kh0[4], kl0[4], kh1[4], kl1[4];
                ldmx4(kh0, kb + AT_KH + (uint32_t)(rowk0 * 272 + segk * 16));
                ldmx4(kh1, kb + AT_KH + (uint32_t)(rowk1 * 272 + segk * 16));
                ldmx4(kl0, kb + AT_KL + (uint32_t)(rowk0 * 272 + segk * 16));
                ldmx4(kl1, kb + AT_KL + (uint32_t)(rowk1 * 272 + segk * 16));
                float* s0 = sacc[4*nbp];     float* s1 = sacc[4*nbp+1];
                float* s2 = sacc[4*nbp+2];   float* s3 = sacc[4*nbp+3];
                mma16816(s0, qa_h, kh0[0], kh0[1]);
                mma16816(s1, qa_h, kh0[2], kh0[3]);
                mma16816(s2, qa_h, kh1[0], kh1[1]);
                mma16816(s3, qa_h, kh1[2], kh1[3]);
                mma16816(s0, qa_l, kh0[0], kh0[1]);
                mma16816(s1, qa_l, kh0[2], kh0[3]);
                mma16816(s2, qa_l, kh1[0], kh1[1]);
                mma16816(s3, qa_l, kh1[2], kh1[3]);
                mma16816(s0, qa_h, kl0[0], kl0[1]);
                mma16816(s1, qa_h, kl0[2], kl0[3]);
                mma16816(s2, qa_h, kl1[0], kl1[1]);
                mma16816(s3, qa_h, kl1[2], kl1[3]);
            }
        }

        // ---- causal mask (only last two tiles can cross the diagonal) ----
        if (kt >= nt - 2) {
#pragma unroll
            for (int j = 0; j < 8; j++)
#pragma unroll
                for (int e = 0; e < 4; e++) {
                    int col = kv0 + j * 8 + 2 * (lane & 3) + (e & 1);
                    int row = q0 + wid * 16 + (lane >> 2) + 8 * (e >> 1);
                    if (col > row) sacc[j][e] = -1e30f;
                }
        }

        // ---- online softmax (base-2; log2e folded into Q scale) ----
        float alph[2];
#pragma unroll
        for (int half = 0; half < 2; half++) {
            float mx = -1e30f;
#pragma unroll
            for (int j = 0; j < 8; j++)
                mx = fmaxf(mx, fmaxf(sacc[j][2*half], sacc[j][2*half+1]));
            mx = fmaxf(mx, __shfl_xor_sync(0xffffffffu, mx, 1));
            mx = fmaxf(mx, __shfl_xor_sync(0xffffffffu, mx, 2));
            float mo = mrow[half];
            float mn = fmaxf(mo, mx);
            float al = fexp2(mo - mn);
            float sum = 0.f;
#pragma unroll
            for (int j = 0; j < 8; j++) {
                float p0 = fexp2(sacc[j][2*half]   - mn);
                float p1 = fexp2(sacc[j][2*half+1] - mn);
                sacc[j][2*half] = p0; sacc[j][2*half+1] = p1;
                sum += p0 + p1;
            }
            sum += __shfl_xor_sync(0xffffffffu, sum, 1);
            sum += __shfl_xor_sync(0xffffffffu, sum, 2);
            mrow[half] = mn;
            lrow[half] = lrow[half] * al + sum;
            alph[half] = al;
        }
#pragma unroll
        for (int n = 0; n < 16; n++) {
            oacc[n][0] *= alph[0]; oacc[n][1] *= alph[0];
            oacc[n][2] *= alph[1]; oacc[n][3] *= alph[1];
        }

        // ---- PV (fp16): O += Ph*V + Pl*V, P split hi/lo in fp16 ----
#pragma unroll
        for (int kk = 0; kk < 4; kk++) {
            uint32_t pah[4], pal[4];
#pragma unroll
            for (int r = 0; r < 4; r++) {
                int jj = 2*kk + (r >> 1);
                float a0 = sacc[jj][(r & 1) * 2 + 0];
                float a1 = sacc[jj][(r & 1) * 2 + 1];
                uint32_t hp = pack_f16x2(a0, a1);
                union { uint32_t u; __half2 h; } cv; cv.u = hp;
                float h0f = __half2float(cv.h.x);
                float h1f = __half2float(cv.h.y);
                pah[r] = hp;
                pal[r] = pack_f16x2(a0 - h0f, a1 - h1f);
            }
            int rowv = kk * 16 + ((lane >> 3) & 1) * 8 + (lane & 7);
            int colb = (lane >> 4) * 8;   // within 16-col group
#pragma unroll
            for (int nnp = 0; nnp < 4; nnp++) {
                uint32_t va0 = (uint32_t)(rowv * 272 + ((2*nnp)   * 16 + colb) * 2);
                uint32_t va1 = (uint32_t)(rowv * 272 + ((2*nnp+1) * 16 + colb) * 2);
                uint32_t v0f[4], v1f[4];
                ldmx4t(v0f, kb + AT_V + va0);
                ldmx4t(v1f, kb + AT_V + va1);
                float* o0 = oacc[4*nnp];     float* o1 = oacc[4*nnp+1];
                float* o2 = oacc[4*nnp+2];   float* o3 = oacc[4*nnp+3];
                mma16816f(o0, pah, v0f[0], v0f[1]);
                mma16816f(o1, pah, v0f[2], v0f[3]);
                mma16816f(o2, pah, v1f[0], v1f[1]);
                mma16816f(o3, pah, v1f[2], v1f[3]);
                mma16816f(o0, pal, v0f[0], v0f[1]);
                mma16816f(o1, pal, v0f[2], v0f[3]);
                mma16816f(o2, pal, v1f[0], v1f[1]);
                mma16816f(o3, pal, v1f[2], v1f[3]);
            }
        }

        __syncthreads();
        if (kt + 2 < nt) attn_issue_kv(sb, kt & 1, bh, (kt + 2) * 64, tid, Kh, Kl, Vf);
    }

    // ---- epilogue: ctx = O / l, write bf16 hi/lo at [b*S+s][h*D+d] ----
    const int b = bh >> 4, h = bh & 15;
#pragma unroll
    for (int half = 0; half < 2; half++) {
        float inv = 1.0f / lrow[half];
        int s = q0 + wid * 16 + (lane >> 2) + 8 * half;
        size_t base = ((size_t)b * S_ + s) * (size_t)E_ + h * D_;
#pragma unroll
        for (int nn = 0; nn < 16; nn++) {
            int c = nn * 8 + 2 * (lane & 3);
            float v0 = oacc[nn][2*half]   * inv;
            float v1 = oacc[nn][2*half+1] * inv;
            __nv_bfloat16 h0 = __float2bfloat16(v0);
            __nv_bfloat16 h1 = __float2bfloat16(v1);
            __nv_bfloat16 l0 = __float2bfloat16(v0 - __bfloat162float(h0));
            __nv_bfloat16 l1 = __float2bfloat16(v1 - __bfloat162float(h1));
            *(__nv_bfloat162*)(Chi + base + c) = __halves2bfloat162(h0, h1);
            *(__nv_bfloat162*)(Clo + base + c) = __halves2bfloat162(l0, l1);
        }
    }
}

// ---------------------------------------------------------------------------
extern "C" void kernel_launch(void* const* d_in, const int* in_sizes, int n_in,
                              void* d_out, int out_size)
{
    const float* q  = (const float*)d_in[0];
    const float* k  = (const float*)d_in[1];
    const float* v  = (const float*)d_in[2];
    const float* Wq = (const float*)d_in[4];
    const float* Wk = (const float*)d_in[5];
    const float* Wv = (const float*)d_in[6];
    const float* Wo = (const float*)d_in[7];
    float* out = (float*)d_out;

    __nv_bfloat16 *qh,*ql,*kh,*kl,*vh,*vl;
    __nv_bfloat16 *wqh,*wql,*wkh,*wkl,*wvh,*wvl,*woh,*wol;
    __nv_bfloat16 *Qph,*Qpl,*Kph,*Kpl,*ch,*cl;
    __half *Vpf;
    cudaGetSymbolAddress((void**)&qh, g_qh);  cudaGetSymbolAddress((void**)&ql, g_ql);
    cudaGetSymbolAddress((void**)&kh, g_kh);  cudaGetSymbolAddress((void**)&kl, g_kl);
    cudaGetSymbolAddress((void**)&vh, g_vh);  cudaGetSymbolAddress((void**)&vl, g_vl);
    cudaGetSymbolAddress((void**)&wqh, g_wqh); cudaGetSymbolAddress((void**)&wql, g_wql);
    cudaGetSymbolAddress((void**)&wkh, g_wkh); cudaGetSymbolAddress((void**)&wkl, g_wkl);
    cudaGetSymbolAddress((void**)&wvh, g_wvh); cudaGetSymbolAddress((void**)&wvl, g_wvl);
    cudaGetSymbolAddress((void**)&woh, g_woh); cudaGetSymbolAddress((void**)&wol, g_wol);
    cudaGetSymbolAddress((void**)&Qph, g_Qh);  cudaGetSymbolAddress((void**)&Qpl, g_Ql);
    cudaGetSymbolAddress((void**)&Kph, g_Kh);  cudaGetSymbolAddress((void**)&Kpl, g_Kl);
    cudaGetSymbolAddress((void**)&Vpf, g_Vf);
    cudaGetSymbolAddress((void**)&ch, g_ch);   cudaGetSymbolAddress((void**)&cl, g_cl);

    cudaFuncSetAttribute(gemm_hmma, cudaFuncAttributeMaxDynamicSharedMemorySize, GEMM_SMEM);
    cudaFuncSetAttribute(attn_hmma, cudaFuncAttributeMaxDynamicSharedMemorySize, ATTN_SMEM);

    const int nx4 = M_ * K_ / 4;
    const int nw4 = N_ * K_ / 4;

    split3_kernel<<<dim3(nx4/256, 3), 256>>>(q, qh, ql, k, kh, kl, v, vh, vl, nx4);
    split4_kernel<<<dim3(nw4/256, 4), 256>>>(Wq, wqh, wql, Wk, wkh, wkl,
                                             Wv, wvh, wvl, Wo, woh, wol, nw4);

    // scale = log2(e)/sqrt(D): softmax computed base-2 is then exactly softmax(s)
    const float qscale = 0.12751744154070513f;
    dim3 gg(N_/128, M_/128);   // (16, 32)

    gemm_hmma<<<gg, 128, GEMM_SMEM>>>(qh, ql, wqh, wql, nullptr, Qph, Qpl, nullptr, 1, qscale);
    gemm_hmma<<<gg, 128, GEMM_SMEM>>>(kh, kl, wkh, wkl, nullptr, Kph, Kpl, nullptr, 1, 1.0f);
    gemm_hmma<<<gg, 128, GEMM_SMEM>>>(vh, vl, wvh, wvl, nullptr, nullptr, nullptr, Vpf, 2, 1.0f);

    attn_hmma<<<dim3(S_/128, B_*H_), 256, ATTN_SMEM>>>(Qph, Qpl, Kph, Kpl, Vpf, ch, cl);

    gemm_hmma<<<gg, 128, GEMM_SMEM>>>(ch, cl, woh, wol, out, nullptr, nullptr, nullptr, 0, 1.0f);
}

// round 15
// speedup vs baseline: 1.3666x; 1.1286x over previous
#include <cuda_runtime.h>
#include <cuda_bf16.h>
#include <cuda_fp16.h>
#include <math.h>
#include <cstdint>

static constexpr int B_ = 2, S_ = 2048, E_ = 2048, H_ = 16, D_ = 128;
static constexpr int M_ = B_ * S_;   // 4096
static constexpr int N_ = E_;        // 2048
static constexpr int K_ = E_;        // 2048

// ---------------- scratch (__device__ globals: allocation-free rule) --------
// bf16 path (score-critical): q,k activations + Wq,Wk
__device__ __nv_bfloat16 g_qh[M_*K_], g_ql[M_*K_];
__device__ __nv_bfloat16 g_kh[M_*K_], g_kl[M_*K_];
__device__ __nv_bfloat16 g_wqh[N_*K_], g_wql[N_*K_];
__device__ __nv_bfloat16 g_wkh[N_*K_], g_wkl[N_*K_];
// fp16 path (value-critical only): v, Wv, Wo, ctx
__device__ __half g_vfh[M_*K_], g_vfl[M_*K_];
__device__ __half g_wvf[N_*K_], g_wof[N_*K_];
__device__ __half g_chf[M_*E_], g_clf[M_*E_];
// projections, head-split [B][H][S][D]
__device__ __nv_bfloat16 g_Qh[B_*H_*S_*D_], g_Ql[B_*H_*S_*D_];
__device__ __nv_bfloat16 g_Kh[B_*H_*S_*D_], g_Kl[B_*H_*S_*D_];
__device__ __half        g_Vf[B_*H_*S_*D_];

// ---------------- helpers ---------------------------------------------------
__device__ __forceinline__ uint32_t smem_u32(const void* p) {
    uint32_t a;
    asm("{ .reg .u64 t; cvta.to.shared.u64 t, %1; cvt.u32.u64 %0, t; }" : "=r"(a) : "l"(p));
    return a;
}
__device__ __forceinline__ void ldmx4(uint32_t* r, uint32_t addr) {
    asm volatile("ldmatrix.sync.aligned.m8n8.x4.shared.b16 {%0,%1,%2,%3}, [%4];"
        : "=r"(r[0]), "=r"(r[1]), "=r"(r[2]), "=r"(r[3]) : "r"(addr));
}
__device__ __forceinline__ void ldmx4t(uint32_t* r, uint32_t addr) {
    asm volatile("ldmatrix.sync.aligned.m8n8.x4.trans.shared.b16 {%0,%1,%2,%3}, [%4];"
        : "=r"(r[0]), "=r"(r[1]), "=r"(r[2]), "=r"(r[3]) : "r"(addr));
}
__device__ __forceinline__ void mma16816(float* c, const uint32_t* a, uint32_t b0, uint32_t b1) {
    asm volatile("mma.sync.aligned.m16n8k16.row.col.f32.bf16.bf16.f32 "
        "{%0,%1,%2,%3}, {%4,%5,%6,%7}, {%8,%9}, {%0,%1,%2,%3};"
        : "+f"(c[0]), "+f"(c[1]), "+f"(c[2]), "+f"(c[3])
        : "r"(a[0]), "r"(a[1]), "r"(a[2]), "r"(a[3]), "r"(b0), "r"(b1));
}
__device__ __forceinline__ void mma16816f(float* c, const uint32_t* a, uint32_t b0, uint32_t b1) {
    asm volatile("mma.sync.aligned.m16n8k16.row.col.f32.f16.f16.f32 "
        "{%0,%1,%2,%3}, {%4,%5,%6,%7}, {%8,%9}, {%0,%1,%2,%3};"
        : "+f"(c[0]), "+f"(c[1]), "+f"(c[2]), "+f"(c[3])
        : "r"(a[0]), "r"(a[1]), "r"(a[2]), "r"(a[3]), "r"(b0), "r"(b1));
}
__device__ __forceinline__ uint32_t pack_f16x2(float lo, float hi) {
    uint32_t d;
    asm("cvt.rn.f16x2.f32 %0, %1, %2;" : "=r"(d) : "f"(hi), "f"(lo));
    return d;
}
// fast exp2 on the FMA pipe (no MUFU). t <= 0 expected; clamped at -80.
__device__ __forceinline__ float fexp2(float t) {
    t = fmaxf(t, -80.0f);
    float r  = __fadd_rn(t, 12582912.0f);         // 1.5*2^23 magic round
    int   i  = __float_as_int(r) - 0x4B400000;
    float rf = __fadd_rn(r, -12582912.0f);
    float f  = __fadd_rn(t, -rf);                 // f in [-0.5, 0.5]
    float p  = 0.0013333558f;
    p = fmaf(p, f, 0.0096181291f);
    p = fmaf(p, f, 0.0555041087f);
    p = fmaf(p, f, 0.2402265069f);
    p = fmaf(p, f, 0.6931471806f);
    p = fmaf(p, f, 1.0f);
    return __int_as_float(__float_as_int(p) + (i << 23));
}

// ---------------- conversion kernels ----------------------------------------
__device__ __forceinline__ void split_one_bf(const float* __restrict__ x,
    __nv_bfloat16* __restrict__ hi, __nv_bfloat16* __restrict__ lo, int i)
{
    float4 v = ((const float4*)x)[i];
    __nv_bfloat16 h0 = __float2bfloat16(v.x);
    __nv_bfloat16 h1 = __float2bfloat16(v.y);
    __nv_bfloat16 h2 = __float2bfloat16(v.z);
    __nv_bfloat16 h3 = __float2bfloat16(v.w);
    __nv_bfloat16 l0 = __float2bfloat16(v.x - __bfloat162float(h0));
    __nv_bfloat16 l1 = __float2bfloat16(v.y - __bfloat162float(h1));
    __nv_bfloat16 l2 = __float2bfloat16(v.z - __bfloat162float(h2));
    __nv_bfloat16 l3 = __float2bfloat16(v.w - __bfloat162float(h3));
    ((__nv_bfloat162*)hi)[i*2]   = __halves2bfloat162(h0, h1);
    ((__nv_bfloat162*)hi)[i*2+1] = __halves2bfloat162(h2, h3);
    ((__nv_bfloat162*)lo)[i*2]   = __halves2bfloat162(l0, l1);
    ((__nv_bfloat162*)lo)[i*2+1] = __halves2bfloat162(l2, l3);
}

// q,k (or Wq,Wk): bf16 hi/lo, two tensors per launch
__global__ __launch_bounds__(256)
void split2_bf16(const float* __restrict__ x0, __nv_bfloat16* h0, __nv_bfloat16* l0,
                 const float* __restrict__ x1, __nv_bfloat16* h1, __nv_bfloat16* l1,
                 int n4)
{
    int i = blockIdx.x * 256 + threadIdx.x;
    if (i >= n4) return;
    if (blockIdx.y == 0) split_one_bf(x0, h0, l0, i);
    else                 split_one_bf(x1, h1, l1, i);
}

// v: fp16 hi/lo split
__global__ __launch_bounds__(256)
void split_f16(const float* __restrict__ x, __half* __restrict__ hi,
               __half* __restrict__ lo, int n4)
{
    int i = blockIdx.x * 256 + threadIdx.x;
    if (i >= n4) return;
    float4 v = ((const float4*)x)[i];
    __half h0 = __float2half_rn(v.x);
    __half h1 = __float2half_rn(v.y);
    __half h2 = __float2half_rn(v.z);
    __half h3 = __float2half_rn(v.w);
    __half l0 = __float2half_rn(v.x - __half2float(h0));
    __half l1 = __float2half_rn(v.y - __half2float(h1));
    __half l2 = __float2half_rn(v.z - __half2float(h2));
    __half l3 = __float2half_rn(v.w - __half2float(h3));
    ((__half2*)hi)[i*2]   = __halves2half2(h0, h1);
    ((__half2*)hi)[i*2+1] = __halves2half2(h2, h3);
    ((__half2*)lo)[i*2]   = __halves2half2(l0, l1);
    ((__half2*)lo)[i*2+1] = __halves2half2(l2, l3);
}

// Wv, Wo: single fp16 conversion, two tensors per launch
__global__ __launch_bounds__(256)
void conv2_f16(const float* __restrict__ x0, __half* __restrict__ y0,
               const float* __restrict__ x1, __half* __restrict__ y1,
               int n4)
{
    int i = blockIdx.x * 256 + threadIdx.x;
    if (i >= n4) return;
    const float* x = blockIdx.y ? x1 : x0;
    __half* y = blockIdx.y ? y1 : y0;
    float4 v = ((const float4*)x)[i];
    ((__half2*)y)[i*2]   = __floats2half2_rn(v.x, v.y);
    ((__half2*)y)[i*2+1] = __floats2half2_rn(v.z, v.w);
}

// ---------------- bf16 HMMA GEMM (3-pass, score path: Q/K projections) ------
// R9 config: 128x128 tile, BK=32, 128 threads (4 warps 64x64), 4-stage cp.async.
static constexpr int GEMM_SMEM = 4 * 16384;   // 65536

__global__ __launch_bounds__(128, 2)
void gemm_bf16(const __nv_bfloat16* __restrict__ Ah, const __nv_bfloat16* __restrict__ Al,
               const __nv_bfloat16* __restrict__ Wh, const __nv_bfloat16* __restrict__ Wl,
               __nv_bfloat16* __restrict__ Chi, __nv_bfloat16* __restrict__ Clo,
               float scale)
{
    extern __shared__ char sm[];
    const uint32_t sbase = smem_u32(sm);
    const int tid  = threadIdx.x;
    const int lane = tid & 31, wid = tid >> 5;
    const int wm = wid & 1, wn = wid >> 1;
    const int m0 = blockIdx.y * 128;
    const int n0 = blockIdx.x * 128;

    float acc[4][8][4];
#pragma unroll
    for (int i = 0; i < 4; i++)
#pragma unroll
        for (int j = 0; j < 8; j++)
#pragma unroll
            for (int t = 0; t < 4; t++) acc[i][j][t] = 0.f;

    const int crow = tid >> 2, cseg = tid & 3;
    const int NITER = 192;

#define G_ISSUE(it) do { \
        int pass_ = (it) >> 6; int kb_ = ((it) & 63) << 5; \
        const __nv_bfloat16* Ap_ = (pass_ == 2) ? Al : Ah; \
        const __nv_bfloat16* Wp_ = (pass_ == 1) ? Wl : Wh; \
        uint32_t st_ = sbase + (uint32_t)(((it) & 3) * 16384); \
        _Pragma("unroll") \
        for (int j_ = 0; j_ < 4; j_++) { \
            int row_ = crow + j_ * 32; \
            uint32_t off_ = (uint32_t)row_ * 64u + (uint32_t)((cseg ^ ((row_ >> 1) & 3)) << 4); \
            const void* ga_ = Ap_ + (size_t)(m0 + row_) * K_ + kb_ + cseg * 8; \
            const void* gb_ = Wp_ + (size_t)(n0 + row_) * K_ + kb_ + cseg * 8; \
            asm volatile("cp.async.cg.shared.global [%0], [%1], 16;" :: "r"(st_ + off_), "l"(ga_)); \
            asm volatile("cp.async.cg.shared.global [%0], [%1], 16;" :: "r"(st_ + 8192u + off_), "l"(gb_)); \
        } \
        asm volatile("cp.async.commit_group;"); \
    } while (0)

    G_ISSUE(0); G_ISSUE(1); G_ISSUE(2);

    const int rowA0 = wm * 64 + (lane & 7) + (lane & 8);
    const int asegb = (lane >> 4);
    const int rowB0 = wn * 64 + (lane & 7) + ((lane >> 4) << 3);
    const int bsegb = (lane >> 3) & 1;

    for (int it = 0; it < NITER; it++) {
        if (it < NITER - 2)      { asm volatile("cp.async.wait_group 2;" ::: "memory"); }
        else if (it == NITER - 2){ asm volatile("cp.async.wait_group 1;" ::: "memory"); }
        else                     { asm volatile("cp.async.wait_group 0;" ::: "memory"); }
        __syncthreads();
        if (it + 3 < NITER) G_ISSUE(it + 3);

        const uint32_t ab = sbase + (uint32_t)((it & 3) * 16384);
        const uint32_t bb = ab + 8192u;

#pragma unroll
        for (int ks = 0; ks < 2; ks++) {
            uint32_t a[4][4];
#pragma unroll
            for (int mt = 0; mt < 4; mt++) {
                int row = rowA0 + mt * 16;
                int sl = ks * 2 + asegb;
                ldmx4(a[mt], ab + (uint32_t)row * 64u + (uint32_t)((sl ^ ((row >> 1) & 3)) << 4));
            }
#pragma unroll
            for (int nb = 0; nb < 4; nb++) {
                int row = rowB0 + nb * 16;
                int sl = ks * 2 + bsegb;
                uint32_t b[4];
                ldmx4(b, bb + (uint32_t)row * 64u + (uint32_t)((sl ^ ((row >> 1) & 3)) << 4));
#pragma unroll
                for (int mt = 0; mt < 4; mt++) {
                    mma16816(acc[mt][2*nb],   a[mt], b[0], b[1]);
                    mma16816(acc[mt][2*nb+1], a[mt], b[2], b[3]);
                }
            }
        }
    }
#undef G_ISSUE

    // epilogue: bf16 hi/lo head-split, scaled
#pragma unroll
    for (int mt = 0; mt < 4; mt++) {
#pragma unroll
        for (int half = 0; half < 2; half++) {
            int m = m0 + wm * 64 + mt * 16 + (lane >> 2) + half * 8;
            int b = m >> 11, s = m & (S_ - 1);
            int h = blockIdx.x;
            size_t base = (((size_t)(b * H_ + h)) * S_ + s) * (size_t)D_;
#pragma unroll
            for (int n8 = 0; n8 < 8; n8++) {
                int c = wn * 64 + n8 * 8 + 2 * (lane & 3);
                float v0 = acc[mt][n8][half*2]   * scale;
                float v1 = acc[mt][n8][half*2+1] * scale;
                __nv_bfloat16 h0 = __float2bfloat16(v0);
                __nv_bfloat16 h1 = __float2bfloat16(v1);
                __nv_bfloat16 l0 = __float2bfloat16(v0 - __bfloat162float(h0));
                __nv_bfloat16 l1 = __float2bfloat16(v1 - __bfloat162float(h1));
                *(__nv_bfloat162*)(Chi + base + c) = __halves2bfloat162(h0, h1);
                *(__nv_bfloat162*)(Clo + base + c) = __halves2bfloat162(l0, l1);
            }
        }
    }
}

// ---------------- fp16 HMMA GEMM (2-pass, value path: V / out projections) --
// Same pipeline shape; A = fp16 hi/lo, W = single fp16, 128 iters.
// mode: 0 = fp32 row-major out; 2 = fp16 single head-split out.
__global__ __launch_bounds__(128, 2)
void gemm_f16(const __half* __restrict__ Ah, const __half* __restrict__ Al,
              const __half* __restrict__ W,
              float* __restrict__ Cf, __half* __restrict__ Cf16, int mode)
{
    extern __shared__ char sm[];
    const uint32_t sbase = smem_u32(sm);
    const int tid  = threadIdx.x;
    const int lane = tid & 31, wid = tid >> 5;
    const int wm = wid & 1, wn = wid >> 1;
    const int m0 = blockIdx.y * 128;
    const int n0 = blockIdx.x * 128;

    float acc[4][8][4];
#pragma unroll
    for (int i = 0; i < 4; i++)
#pragma unroll
        for (int j = 0; j < 8; j++)
#pragma unroll
            for (int t = 0; t < 4; t++) acc[i][j][t] = 0.f;

    const int crow = tid >> 2, cseg = tid & 3;
    const int NITER = 128;   // 2 passes x 64 k-iters

#define G_ISSUE(it) do { \
        int pass_ = (it) >> 6; int kb_ = ((it) & 63) << 5; \
        const __half* Ap_ = pass_ ? Al : Ah; \
        uint32_t st_ = sbase + (uint32_t)(((it) & 3) * 16384); \
        _Pragma("unroll") \
        for (int j_ = 0; j_ < 4; j_++) { \
            int row_ = crow + j_ * 32; \
            uint32_t off_ = (uint32_t)row_ * 64u + (uint32_t)((cseg ^ ((row_ >> 1) & 3)) << 4); \
            const void* ga_ = Ap_ + (size_t)(m0 + row_) * K_ + kb_ + cseg * 8; \
            const void* gb_ = W + (size_t)(n0 + row_) * K_ + kb_ + cseg * 8; \
            asm volatile("cp.async.cg.shared.global [%0], [%1], 16;" :: "r"(st_ + off_), "l"(ga_)); \
            asm volatile("cp.async.cg.shared.global [%0], [%1], 16;" :: "r"(st_ + 8192u + off_), "l"(gb_)); \
        } \
        asm volatile("cp.async.commit_group;"); \
    } while (0)

    G_ISSUE(0); G_ISSUE(1); G_ISSUE(2);

    const int rowA0 = wm * 64 + (lane & 7) + (lane & 8);
    const int asegb = (lane >> 4);
    const int rowB0 = wn * 64 + (lane & 7) + ((lane >> 4) << 3);
    const int bsegb = (lane >> 3) & 1;

    for (int it = 0; it < NITER; it++) {
        if (it < NITER - 2)      { asm volatile("cp.async.wait_group 2;" ::: "memory"); }
        else if (it == NITER - 2){ asm volatile("cp.async.wait_group 1;" ::: "memory"); }
        else                     { asm volatile("cp.async.wait_group 0;" ::: "memory"); }
        __syncthreads();
        if (it + 3 < NITER) G_ISSUE(it + 3);

        const uint32_t ab = sbase + (uint32_t)((it & 3) * 16384);
        const uint32_t bb = ab + 8192u;

#pragma unroll
        for (int ks = 0; ks < 2; ks++) {
            uint32_t a[4][4];
#pragma unroll
            for (int mt = 0; mt < 4; mt++) {
                int row = rowA0 + mt * 16;
                int sl = ks * 2 + asegb;
                ldmx4(a[mt], ab + (uint32_t)row * 64u + (uint32_t)((sl ^ ((row >> 1) & 3)) << 4));
            }
#pragma unroll
            for (int nb = 0; nb < 4; nb++) {
                int row = rowB0 + nb * 16;
                int sl = ks * 2 + bsegb;
                uint32_t b[4];
                ldmx4(b, bb + (uint32_t)row * 64u + (uint32_t)((sl ^ ((row >> 1) & 3)) << 4));
#pragma unroll
                for (int mt = 0; mt < 4; mt++) {
                    mma16816f(acc[mt][2*nb],   a[mt], b[0], b[1]);
                    mma16816f(acc[mt][2*nb+1], a[mt], b[2], b[3]);
                }
            }
        }
    }
#undef G_ISSUE

    // epilogue
#pragma unroll
    for (int mt = 0; mt < 4; mt++) {
#pragma unroll
        for (int half = 0; half < 2; half++) {
            int m = m0 + wm * 64 + mt * 16 + (lane >> 2) + half * 8;
            if (mode == 2) {
                int b = m >> 11, s = m & (S_ - 1);
                int h = blockIdx.x;
                size_t base = (((size_t)(b * H_ + h)) * S_ + s) * (size_t)D_;
#pragma unroll
                for (int n8 = 0; n8 < 8; n8++) {
                    int c = wn * 64 + n8 * 8 + 2 * (lane & 3);
                    __half2 hv = __floats2half2_rn(acc[mt][n8][half*2],
                                                   acc[mt][n8][half*2+1]);
                    *(__half2*)(Cf16 + base + c) = hv;
                }
            } else {
#pragma unroll
                for (int n8 = 0; n8 < 8; n8++) {
                    int c = wn * 64 + n8 * 8 + 2 * (lane & 3);
                    float2 v;
                    v.x = acc[mt][n8][half*2];
                    v.y = acc[mt][n8][half*2+1];
                    *(float2*)(Cf + (size_t)m * N_ + n0 + c) = v;
                }
            }
        }
    }
}

// ---------------- HMMA flash attention --------------------------------------
// CTA: 256 threads (8 warps, 16 q-rows each), Br=128, Bc=64, D=128.
// Scores 3-pass bf16 hi/lo; PV 2-pass fp16. ctx written fp16 hi/lo.
static constexpr int AT_QH  = 0;
static constexpr int AT_QL  = 34816;
static constexpr int AT_KV0 = 69632;
static constexpr int AT_KH = 0, AT_KL = 17408, AT_V = 34816;
static constexpr int KV_STRIDE = 52224;
static constexpr int ATTN_SMEM = AT_KV0 + 2 * KV_STRIDE;   // 174080

__device__ __forceinline__ void attn_issue_kv(
    uint32_t sb, int stage, int bh, int kv0, int tid,
    const __nv_bfloat16* Kh, const __nv_bfloat16* Kl, const __half* Vf)
{
    uint32_t kb = sb + AT_KV0 + (uint32_t)(stage * KV_STRIDE);
    const size_t ebase = ((size_t)bh * S_ + kv0) * D_;
    const char* srcs[3] = {(const char*)(Kh + ebase), (const char*)(Kl + ebase),
                           (const char*)(Vf + ebase)};
    const uint32_t offs[3] = {AT_KH, AT_KL, AT_V};
#pragma unroll
    for (int m = 0; m < 3; m++) {
#pragma unroll
        for (int j = 0; j < 4; j++) {
            int idx = tid + j * 256;
            int row = idx >> 4, seg = idx & 15;
            const void* g = srcs[m] + (size_t)row * (D_ * 2) + seg * 16;
            asm volatile("cp.async.cg.shared.global [%0], [%1], 16;"
                :: "r"(kb + offs[m] + (uint32_t)(row * 272 + seg * 16)), "l"(g));
        }
    }
    asm volatile("cp.async.commit_group;");
}

__global__ __launch_bounds__(256)
void attn_hmma(const __nv_bfloat16* __restrict__ Qh, const __nv_bfloat16* __restrict__ Ql,
               const __nv_bfloat16* __restrict__ Kh, const __nv_bfloat16* __restrict__ Kl,
               const __half* __restrict__ Vf,
               __half* __restrict__ Chi, __half* __restrict__ Clo)
{
    extern __shared__ char sm[];
    const uint32_t sb = smem_u32(sm);
    const int tid = threadIdx.x;
    const int lane = tid & 31, wid = tid >> 5;
    const int qt = (int)gridDim.x - 1 - (int)blockIdx.x;   // heavy tiles first
    const int bh = blockIdx.y;
    const int q0 = qt * 128;
    const int nt = 2 * qt + 2;

    // ---- load Q (hi+lo) as its own cp.async group ----
    {
        const __nv_bfloat16* qsrc[2] = {Qh + ((size_t)bh * S_ + q0) * D_,
                                        Ql + ((size_t)bh * S_ + q0) * D_};
        const uint32_t qoff[2] = {AT_QH, AT_QL};
#pragma unroll
        for (int m = 0; m < 2; m++) {
#pragma unroll
            for (int j = 0; j < 8; j++) {
                int idx = tid + j * 256;
                int row = idx >> 4, seg = idx & 15;
                const void* g = qsrc[m] + (size_t)row * D_ + seg * 8;
                asm volatile("cp.async.cg.shared.global [%0], [%1], 16;"
                    :: "r"(sb + qoff[m] + (uint32_t)(row * 272 + seg * 16)), "l"(g));
            }
        }
        asm volatile("cp.async.commit_group;");
    }
    attn_issue_kv(sb, 0, bh, 0, tid, Kh, Kl, Vf);
    if (nt > 1) attn_issue_kv(sb, 1, bh, 64, tid, Kh, Kl, Vf);

    float oacc[16][4];
#pragma unroll
    for (int n = 0; n < 16; n++)
#pragma unroll
        for (int t = 0; t < 4; t++) oacc[n][t] = 0.f;
    float mrow[2] = {-1e30f, -1e30f};
    float lrow[2] = {0.f, 0.f};

    for (int kt = 0; kt < nt; kt++) {
        const int kv0 = kt * 64;
        if (kt + 1 < nt) { asm volatile("cp.async.wait_group 1;" ::: "memory"); }
        else             { asm volatile("cp.async.wait_group 0;" ::: "memory"); }
        __syncthreads();
        const uint32_t kb = sb + AT_KV0 + (uint32_t)((kt & 1) * KV_STRIDE);

        // ---- scores: S = Qh*Kh^T + Qh*Kl^T + Ql*Kh^T (pairs, dist-4) ----
        float sacc[8][4];
#pragma unroll
        for (int j = 0; j < 8; j++)
#pragma unroll
            for (int t = 0; t < 4; t++) sacc[j][t] = 0.f;

#pragma unroll
        for (int ks = 0; ks < 8; ks++) {
            uint32_t qa_h[4], qa_l[4];
            {
                int row = wid * 16 + (lane & 7) + (lane & 8);
                int seg = ks * 2 + (lane >> 4);
                ldmx4(qa_h, sb + AT_QH + (uint32_t)(row * 272 + seg * 16));
                ldmx4(qa_l, sb + AT_QL + (uint32_t)(row * 272 + seg * 16));
            }
#pragma unroll
            for (int nbp = 0; nbp < 2; nbp++) {
                int segk = ks * 2 + ((lane >> 3) & 1);
                int rowk0 = (2*nbp)   * 16 + (lane & 7) + ((lane >> 4) << 3);
                int rowk1 = (2*nbp+1) * 16 + (lane & 7) + ((lane >> 4) << 3);
                uint32_t kh0[4], kl0[4], kh1[4], kl1[4];
                ldmx4(kh0, kb + AT_KH + (uint32_t)(rowk0 * 272 + segk * 16));
                ldmx4(kh1, kb + AT_KH + (uint32_t)(rowk1 * 272 + segk * 16));
                ldmx4(kl0, kb + AT_KL + (uint32_t)(rowk0 * 272 + segk * 16));
                ldmx4(kl1, kb + AT_KL + (uint32_t)(rowk1 * 272 + segk * 16));
                float* s0 = sacc[4*nbp];     float* s1 = sacc[4*nbp+1];
                float* s2 = sacc[4*nbp+2];   float* s3 = sacc[4*nbp+3];
                mma16816(s0, qa_h, kh0[0], kh0[1]);
                mma16816(s1, qa_h, kh0[2], kh0[3]);
                mma16816(s2, qa_h, kh1[0], kh1[1]);
                mma16816(s3, qa_h, kh1[2], kh1[3]);
                mma16816(s0, qa_l, kh0[0], kh0[1]);
                mma16816(s1, qa_l, kh0[2], kh0[3]);
                mma16816(s2, qa_l, kh1[0], kh1[1]);
                mma16816(s3, qa_l, kh1[2], kh1[3]);
                mma16816(s0, qa_h, kl0[0], kl0[1]);
                mma16816(s1, qa_h, kl0[2], kl0[3]);
                mma16816(s2, qa_h, kl1[0], kl1[1]);
                mma16816(s3, qa_h, kl1[2], kl1[3]);
            }
        }

        // ---- causal mask (only last two tiles can cross the diagonal) ----
        if (kt >= nt - 2) {
#pragma unroll
            for (int j = 0; j < 8; j++)
#pragma unroll
                for (int e = 0; e < 4; e++) {
                    int col = kv0 + j * 8 + 2 * (lane & 3) + (e & 1);
                    int row = q0 + wid * 16 + (lane >> 2) + 8 * (e >> 1);
                    if (col > row) sacc[j][e] = -1e30f;
                }
        }

        // ---- online softmax (base-2; log2e folded into Q scale) ----
        float alph[2];
#pragma unroll
        for (int half = 0; half < 2; half++) {
            float mx = -1e30f;
#pragma unroll
            for (int j = 0; j < 8; j++)
                mx = fmaxf(mx, fmaxf(sacc[j][2*half], sacc[j][2*half+1]));
            mx = fmaxf(mx, __shfl_xor_sync(0xffffffffu, mx, 1));
            mx = fmaxf(mx, __shfl_xor_sync(0xffffffffu, mx, 2));
            float mo = mrow[half];
            float mn = fmaxf(mo, mx);
            float al = fexp2(mo - mn);
            float sum = 0.f;
#pragma unroll
            for (int j = 0; j < 8; j++) {
                float p0 = fexp2(sacc[j][2*half]   - mn);
                float p1 = fexp2(sacc[j][2*half+1] - mn);
                sacc[j][2*half] = p0; sacc[j][2*half+1] = p1;
                sum += p0 + p1;
            }
            sum += __shfl_xor_sync(0xffffffffu, sum, 1);
            sum += __shfl_xor_sync(0xffffffffu, sum, 2);
            mrow[half] = mn;
            lrow[half] = lrow[half] * al + sum;
            alph[half] = al;
        }
#pragma unroll
        for (int n = 0; n < 16; n++) {
            oacc[n][0] *= alph[0]; oacc[n][1] *= alph[0];
            oacc[n][2] *= alph[1]; oacc[n][3] *= alph[1];
        }

        // ---- PV (fp16): O += Ph*V + Pl*V, P split hi/lo in fp16 ----
#pragma unroll
        for (int kk = 0; kk < 4; kk++) {
            uint32_t pah[4], pal[4];
#pragma unroll
            for (int r = 0; r < 4; r++) {
                int jj = 2*kk + (r >> 1);
                float a0 = sacc[jj][(r & 1) * 2 + 0];
                float a1 = sacc[jj][(r & 1) * 2 + 1];
                uint32_t hp = pack_f16x2(a0, a1);
                union { uint32_t u; __half2 h; } cv; cv.u = hp;
                float h0f = __half2float(cv.h.x);
                float h1f = __half2float(cv.h.y);
                pah[r] = hp;
                pal[r] = pack_f16x2(a0 - h0f, a1 - h1f);
            }
            int rowv = kk * 16 + ((lane >> 3) & 1) * 8 + (lane & 7);
            int colb = (lane >> 4) * 8;
#pragma unroll
            for (int nnp = 0; nnp < 4; nnp++) {
                uint32_t va0 = (uint32_t)(rowv * 272 + ((2*nnp)   * 16 + colb) * 2);
                uint32_t va1 = (uint32_t)(rowv * 272 + ((2*nnp+1) * 16 + colb) * 2);
                uint32_t v0f[4], v1f[4];
                ldmx4t(v0f, kb + AT_V + va0);
                ldmx4t(v1f, kb + AT_V + va1);
                float* o0 = oacc[4*nnp];     float* o1 = oacc[4*nnp+1];
                float* o2 = oacc[4*nnp+2];   float* o3 = oacc[4*nnp+3];
                mma16816f(o0, pah, v0f[0], v0f[1]);
                mma16816f(o1, pah, v0f[2], v0f[3]);
                mma16816f(o2, pah, v1f[0], v1f[1]);
                mma16816f(o3, pah, v1f[2], v1f[3]);
                mma16816f(o0, pal, v0f[0], v0f[1]);
                mma16816f(o1, pal, v0f[2], v0f[3]);
                mma16816f(o2, pal, v1f[0], v1f[1]);
                mma16816f(o3, pal, v1f[2], v1f[3]);
            }
        }

        __syncthreads();
        if (kt + 2 < nt) attn_issue_kv(sb, kt & 1, bh, (kt + 2) * 64, tid, Kh, Kl, Vf);
    }

    // ---- epilogue: ctx = O / l, write fp16 hi/lo at [b*S+s][h*D+d] ----
    const int b = bh >> 4, h = bh & 15;
#pragma unroll
    for (int half = 0; half < 2; half++) {
        float inv = 1.0f / lrow[half];
        int s = q0 + wid * 16 + (lane >> 2) + 8 * half;
        size_t base = ((size_t)b * S_ + s) * (size_t)E_ + h * D_;
#pragma unroll
        for (int nn = 0; nn < 16; nn++) {
            int c = nn * 8 + 2 * (lane & 3);
            float v0 = oacc[nn][2*half]   * inv;
            float v1 = oacc[nn][2*half+1] * inv;
            __half h0 = __float2half_rn(v0);
            __half h1 = __float2half_rn(v1);
            __half l0 = __float2half_rn(v0 - __half2float(h0));
            __half l1 = __float2half_rn(v1 - __half2float(h1));
            *(__half2*)(Chi + base + c) = __halves2half2(h0, h1);
            *(__half2*)(Clo + base + c) = __halves2half2(l0, l1);
        }
    }
}

// ---------------------------------------------------------------------------
extern "C" void kernel_launch(void* const* d_in, const int* in_sizes, int n_in,
                              void* d_out, int out_size)
{
    const float* q  = (const float*)d_in[0];
    const float* k  = (const float*)d_in[1];
    const float* v  = (const float*)d_in[2];
    const float* Wq = (const float*)d_in[4];
    const float* Wk = (const float*)d_in[5];
    const float* Wv = (const float*)d_in[6];
    const float* Wo = (const float*)d_in[7];
    float* out = (float*)d_out;

    __nv_bfloat16 *qh,*ql,*kh,*kl,*wqh,*wql,*wkh,*wkl,*Qph,*Qpl,*Kph,*Kpl;
    __half *vfh,*vfl,*wvf,*wof,*chf,*clf,*Vpf;
    cudaGetSymbolAddress((void**)&qh, g_qh);   cudaGetSymbolAddress((void**)&ql, g_ql);
    cudaGetSymbolAddress((void**)&kh, g_kh);   cudaGetSymbolAddress((void**)&kl, g_kl);
    cudaGetSymbolAddress((void**)&wqh, g_wqh); cudaGetSymbolAddress((void**)&wql, g_wql);
    cudaGetSymbolAddress((void**)&wkh, g_wkh); cudaGetSymbolAddress((void**)&wkl, g_wkl);
    cudaGetSymbolAddress((void**)&vfh, g_vfh); cudaGetSymbolAddress((void**)&vfl, g_vfl);
    cudaGetSymbolAddress((void**)&wvf, g_wvf); cudaGetSymbolAddress((void**)&wof, g_wof);
    cudaGetSymbolAddress((void**)&chf, g_chf); cudaGetSymbolAddress((void**)&clf, g_clf);
    cudaGetSymbolAddress((void**)&Qph, g_Qh);  cudaGetSymbolAddress((void**)&Qpl, g_Ql);
    cudaGetSymbolAddress((void**)&Kph, g_Kh);  cudaGetSymbolAddress((void**)&Kpl, g_Kl);
    cudaGetSymbolAddress((void**)&Vpf, g_Vf);

    cudaFuncSetAttribute(gemm_bf16, cudaFuncAttributeMaxDynamicSharedMemorySize, GEMM_SMEM);
    cudaFuncSetAttribute(gemm_f16, cudaFuncAttributeMaxDynamicSharedMemorySize, GEMM_SMEM);
    cudaFuncSetAttribute(attn_hmma, cudaFuncAttributeMaxDynamicSharedMemorySize, ATTN_SMEM);

    const int nx4 = M_ * K_ / 4;
    const int nw4 = N_ * K_ / 4;

    split2_bf16<<<dim3(nx4/256, 2), 256>>>(q, qh, ql, k, kh, kl, nx4);
    split2_bf16<<<dim3(nw4/256, 2), 256>>>(Wq, wqh, wql, Wk, wkh, wkl, nw4);
    split_f16<<<nx4/256, 256>>>(v, vfh, vfl, nx4);
    conv2_f16<<<dim3(nw4/256, 2), 256>>>(Wv, wvf, Wo, wof, nw4);

    // scale = log2(e)/sqrt(D): softmax computed base-2 is then exactly softmax(s)
    const float qscale = 0.12751744154070513f;
    dim3 gg(N_/128, M_/128);   // (16, 32)

    gemm_bf16<<<gg, 128, GEMM_SMEM>>>(qh, ql, wqh, wql, Qph, Qpl, qscale);
    gemm_bf16<<<gg, 128, GEMM_SMEM>>>(kh, kl, wkh, wkl, Kph, Kpl, 1.0f);
    gemm_f16<<<gg, 128, GEMM_SMEM>>>(vfh, vfl, wvf, nullptr, Vpf, 2);

    attn_hmma<<<dim3(S_/128, B_*H_), 256, ATTN_SMEM>>>(Qph, Qpl, Kph, Kpl, Vpf, chf, clf);

    gemm_f16<<<gg, 128, GEMM_SMEM>>>(chf, clf, wof, out, nullptr, 0);
}

// round 16
// speedup vs baseline: 1.5634x; 1.1440x over previous
#include <cuda_runtime.h>
#include <cuda_bf16.h>
#include <cuda_fp16.h>
#include <math.h>
#include <cstdint>

static constexpr int B_ = 2, S_ = 2048, E_ = 2048, H_ = 16, D_ = 128;
static constexpr int M_ = B_ * S_;   // 4096
static constexpr int N_ = E_;        // 2048
static constexpr int K_ = E_;        // 2048

// ---------------- scratch (__device__ globals: allocation-free rule) --------
// activations fp16 hi/lo
__device__ __half g_qfh[M_*K_], g_qfl[M_*K_];
__device__ __half g_kfh[M_*K_], g_kfl[M_*K_];
__device__ __half g_vfh[M_*K_], g_vfl[M_*K_];
// weights single fp16
__device__ __half g_wqf[N_*K_], g_wkf[N_*K_], g_wvf[N_*K_], g_wof[N_*K_];
// ctx fp16 hi/lo
__device__ __half g_chf[M_*E_], g_clf[M_*E_];
// projections, head-split [B][H][S][D], fp16
__device__ __half g_Qh[B_*H_*S_*D_], g_Ql[B_*H_*S_*D_];
__device__ __half g_Kh[B_*H_*S_*D_], g_Kl[B_*H_*S_*D_];
__device__ __half g_Vf[B_*H_*S_*D_];

// ---------------- helpers ---------------------------------------------------
__device__ __forceinline__ uint32_t smem_u32(const void* p) {
    uint32_t a;
    asm("{ .reg .u64 t; cvta.to.shared.u64 t, %1; cvt.u32.u64 %0, t; }" : "=r"(a) : "l"(p));
    return a;
}
__device__ __forceinline__ void ldmx4(uint32_t* r, uint32_t addr) {
    asm volatile("ldmatrix.sync.aligned.m8n8.x4.shared.b16 {%0,%1,%2,%3}, [%4];"
        : "=r"(r[0]), "=r"(r[1]), "=r"(r[2]), "=r"(r[3]) : "r"(addr));
}
__device__ __forceinline__ void ldmx4t(uint32_t* r, uint32_t addr) {
    asm volatile("ldmatrix.sync.aligned.m8n8.x4.trans.shared.b16 {%0,%1,%2,%3}, [%4];"
        : "=r"(r[0]), "=r"(r[1]), "=r"(r[2]), "=r"(r[3]) : "r"(addr));
}
__device__ __forceinline__ void mma16816f(float* c, const uint32_t* a, uint32_t b0, uint32_t b1) {
    asm volatile("mma.sync.aligned.m16n8k16.row.col.f32.f16.f16.f32 "
        "{%0,%1,%2,%3}, {%4,%5,%6,%7}, {%8,%9}, {%0,%1,%2,%3};"
        : "+f"(c[0]), "+f"(c[1]), "+f"(c[2]), "+f"(c[3])
        : "r"(a[0]), "r"(a[1]), "r"(a[2]), "r"(a[3]), "r"(b0), "r"(b1));
}
__device__ __forceinline__ uint32_t pack_f16x2(float lo, float hi) {
    uint32_t d;
    asm("cvt.rn.f16x2.f32 %0, %1, %2;" : "=r"(d) : "f"(hi), "f"(lo));
    return d;
}
// fast exp2 on the FMA pipe (no MUFU). t <= 0 expected; clamped at -80.
__device__ __forceinline__ float fexp2(float t) {
    t = fmaxf(t, -80.0f);
    float r  = __fadd_rn(t, 12582912.0f);         // 1.5*2^23 magic round
    int   i  = __float_as_int(r) - 0x4B400000;
    float rf = __fadd_rn(r, -12582912.0f);
    float f  = __fadd_rn(t, -rf);                 // f in [-0.5, 0.5]
    float p  = 0.0013333558f;
    p = fmaf(p, f, 0.0096181291f);
    p = fmaf(p, f, 0.0555041087f);
    p = fmaf(p, f, 0.2402265069f);
    p = fmaf(p, f, 0.6931471806f);
    p = fmaf(p, f, 1.0f);
    return __int_as_float(__float_as_int(p) + (i << 23));
}

// ---------------- conversion kernels ----------------------------------------
// activations: fp16 hi/lo split, three tensors per launch
__global__ __launch_bounds__(256)
void split3_f16(const float* __restrict__ x0, __half* h0, __half* l0,
                const float* __restrict__ x1, __half* h1, __half* l1,
                const float* __restrict__ x2, __half* h2, __half* l2,
                int n4)
{
    int i = blockIdx.x * 256 + threadIdx.x;
    if (i >= n4) return;
    const float* x; __half *hi, *lo;
    if (blockIdx.y == 0)      { x = x0; hi = h0; lo = l0; }
    else if (blockIdx.y == 1) { x = x1; hi = h1; lo = l1; }
    else                      { x = x2; hi = h2; lo = l2; }
    float4 v = ((const float4*)x)[i];
    __half a0 = __float2half_rn(v.x);
    __half a1 = __float2half_rn(v.y);
    __half a2 = __float2half_rn(v.z);
    __half a3 = __float2half_rn(v.w);
    __half b0 = __float2half_rn(v.x - __half2float(a0));
    __half b1 = __float2half_rn(v.y - __half2float(a1));
    __half b2 = __float2half_rn(v.z - __half2float(a2));
    __half b3 = __float2half_rn(v.w - __half2float(a3));
    ((__half2*)hi)[i*2]   = __halves2half2(a0, a1);
    ((__half2*)hi)[i*2+1] = __halves2half2(a2, a3);
    ((__half2*)lo)[i*2]   = __halves2half2(b0, b1);
    ((__half2*)lo)[i*2+1] = __halves2half2(b2, b3);
}

// weights: single fp16 conversion, four tensors per launch
__global__ __launch_bounds__(256)
void conv4_f16(const float* __restrict__ x0, __half* y0,
               const float* __restrict__ x1, __half* y1,
               const float* __restrict__ x2, __half* y2,
               const float* __restrict__ x3, __half* y3,
               int n4)
{
    int i = blockIdx.x * 256 + threadIdx.x;
    if (i >= n4) return;
    const float* x; __half* y;
    if (blockIdx.y == 0)      { x = x0; y = y0; }
    else if (blockIdx.y == 1) { x = x1; y = y1; }
    else if (blockIdx.y == 2) { x = x2; y = y2; }
    else                      { x = x3; y = y3; }
    float4 v = ((const float4*)x)[i];
    ((__half2*)y)[i*2]   = __floats2half2_rn(v.x, v.y);
    ((__half2*)y)[i*2+1] = __floats2half2_rn(v.z, v.w);
}

// ---------------- fp16 HMMA GEMM (2-pass: A hi/lo x single-fp16 W) ----------
// R9 pipeline: 128x128 tile, BK=32, 128 threads (4 warps 64x64), 4-stage.
// mode: 0 = fp32 row-major; 1 = fp16 hi/lo head-split (scaled); 2 = fp16 single head-split.
static constexpr int GEMM_SMEM = 4 * 16384;   // 65536

__global__ __launch_bounds__(128, 2)
void gemm_f16(const __half* __restrict__ Ah, const __half* __restrict__ Al,
              const __half* __restrict__ W,
              float* __restrict__ Cf, __half* __restrict__ Chi,
              __half* __restrict__ Clo, __half* __restrict__ Cf16,
              int mode, float scale)
{
    extern __shared__ char sm[];
    const uint32_t sbase = smem_u32(sm);
    const int tid  = threadIdx.x;
    const int lane = tid & 31, wid = tid >> 5;
    const int wm = wid & 1, wn = wid >> 1;
    const int m0 = blockIdx.y * 128;
    const int n0 = blockIdx.x * 128;

    float acc[4][8][4];
#pragma unroll
    for (int i = 0; i < 4; i++)
#pragma unroll
        for (int j = 0; j < 8; j++)
#pragma unroll
            for (int t = 0; t < 4; t++) acc[i][j][t] = 0.f;

    const int crow = tid >> 2, cseg = tid & 3;
    const int NITER = 128;   // 2 passes x 64 k-iters

#define G_ISSUE(it) do { \
        int pass_ = (it) >> 6; int kb_ = ((it) & 63) << 5; \
        const __half* Ap_ = pass_ ? Al : Ah; \
        uint32_t st_ = sbase + (uint32_t)(((it) & 3) * 16384); \
        _Pragma("unroll") \
        for (int j_ = 0; j_ < 4; j_++) { \
            int row_ = crow + j_ * 32; \
            uint32_t off_ = (uint32_t)row_ * 64u + (uint32_t)((cseg ^ ((row_ >> 1) & 3)) << 4); \
            const void* ga_ = Ap_ + (size_t)(m0 + row_) * K_ + kb_ + cseg * 8; \
            const void* gb_ = W + (size_t)(n0 + row_) * K_ + kb_ + cseg * 8; \
            asm volatile("cp.async.cg.shared.global [%0], [%1], 16;" :: "r"(st_ + off_), "l"(ga_)); \
            asm volatile("cp.async.cg.shared.global [%0], [%1], 16;" :: "r"(st_ + 8192u + off_), "l"(gb_)); \
        } \
        asm volatile("cp.async.commit_group;"); \
    } while (0)

    G_ISSUE(0); G_ISSUE(1); G_ISSUE(2);

    const int rowA0 = wm * 64 + (lane & 7) + (lane & 8);
    const int asegb = (lane >> 4);
    const int rowB0 = wn * 64 + (lane & 7) + ((lane >> 4) << 3);
    const int bsegb = (lane >> 3) & 1;

    for (int it = 0; it < NITER; it++) {
        if (it < NITER - 2)      { asm volatile("cp.async.wait_group 2;" ::: "memory"); }
        else if (it == NITER - 2){ asm volatile("cp.async.wait_group 1;" ::: "memory"); }
        else                     { asm volatile("cp.async.wait_group 0;" ::: "memory"); }
        __syncthreads();
        if (it + 3 < NITER) G_ISSUE(it + 3);

        const uint32_t ab = sbase + (uint32_t)((it & 3) * 16384);
        const uint32_t bb = ab + 8192u;

#pragma unroll
        for (int ks = 0; ks < 2; ks++) {
            uint32_t a[4][4];
#pragma unroll
            for (int mt = 0; mt < 4; mt++) {
                int row = rowA0 + mt * 16;
                int sl = ks * 2 + asegb;
                ldmx4(a[mt], ab + (uint32_t)row * 64u + (uint32_t)((sl ^ ((row >> 1) & 3)) << 4));
            }
#pragma unroll
            for (int nb = 0; nb < 4; nb++) {
                int row = rowB0 + nb * 16;
                int sl = ks * 2 + bsegb;
                uint32_t b[4];
                ldmx4(b, bb + (uint32_t)row * 64u + (uint32_t)((sl ^ ((row >> 1) & 3)) << 4));
#pragma unroll
                for (int mt = 0; mt < 4; mt++) {
                    mma16816f(acc[mt][2*nb],   a[mt], b[0], b[1]);
                    mma16816f(acc[mt][2*nb+1], a[mt], b[2], b[3]);
                }
            }
        }
    }
#undef G_ISSUE

    // epilogue
#pragma unroll
    for (int mt = 0; mt < 4; mt++) {
#pragma unroll
        for (int half = 0; half < 2; half++) {
            int m = m0 + wm * 64 + mt * 16 + (lane >> 2) + half * 8;
            if (mode == 1) {
                int b = m >> 11, s = m & (S_ - 1);
                int h = blockIdx.x;
                size_t base = (((size_t)(b * H_ + h)) * S_ + s) * (size_t)D_;
#pragma unroll
                for (int n8 = 0; n8 < 8; n8++) {
                    int c = wn * 64 + n8 * 8 + 2 * (lane & 3);
                    float v0 = acc[mt][n8][half*2]   * scale;
                    float v1 = acc[mt][n8][half*2+1] * scale;
                    __half h0 = __float2half_rn(v0);
                    __half h1 = __float2half_rn(v1);
                    __half l0 = __float2half_rn(v0 - __half2float(h0));
                    __half l1 = __float2half_rn(v1 - __half2float(h1));
                    *(__half2*)(Chi + base + c) = __halves2half2(h0, h1);
                    *(__half2*)(Clo + base + c) = __halves2half2(l0, l1);
                }
            } else if (mode == 2) {
                int b = m >> 11, s = m & (S_ - 1);
                int h = blockIdx.x;
                size_t base = (((size_t)(b * H_ + h)) * S_ + s) * (size_t)D_;
#pragma unroll
                for (int n8 = 0; n8 < 8; n8++) {
                    int c = wn * 64 + n8 * 8 + 2 * (lane & 3);
                    __half2 hv = __floats2half2_rn(acc[mt][n8][half*2],
                                                   acc[mt][n8][half*2+1]);
                    *(__half2*)(Cf16 + base + c) = hv;
                }
            } else {
#pragma unroll
                for (int n8 = 0; n8 < 8; n8++) {
                    int c = wn * 64 + n8 * 8 + 2 * (lane & 3);
                    float2 v;
                    v.x = acc[mt][n8][half*2];
                    v.y = acc[mt][n8][half*2+1];
                    *(float2*)(Cf + (size_t)m * N_ + n0 + c) = v;
                }
            }
        }
    }
}

// ---------------- HMMA flash attention (all fp16) ---------------------------
// CTA: 256 threads (8 warps, 16 q-rows each), Br=128, Bc=64, D=128.
// Scores 3-pass fp16 hi/lo; PV 2-pass fp16. ctx written fp16 hi/lo.
static constexpr int AT_QH  = 0;
static constexpr int AT_QL  = 34816;
static constexpr int AT_KV0 = 69632;
static constexpr int AT_KH = 0, AT_KL = 17408, AT_V = 34816;
static constexpr int KV_STRIDE = 52224;
static constexpr int ATTN_SMEM = AT_KV0 + 2 * KV_STRIDE;   // 174080

__device__ __forceinline__ void attn_issue_kv(
    uint32_t sb, int stage, int bh, int kv0, int tid,
    const __half* Kh, const __half* Kl, const __half* Vf)
{
    uint32_t kb = sb + AT_KV0 + (uint32_t)(stage * KV_STRIDE);
    const size_t ebase = ((size_t)bh * S_ + kv0) * D_;
    const char* srcs[3] = {(const char*)(Kh + ebase), (const char*)(Kl + ebase),
                           (const char*)(Vf + ebase)};
    const uint32_t offs[3] = {AT_KH, AT_KL, AT_V};
#pragma unroll
    for (int m = 0; m < 3; m++) {
#pragma unroll
        for (int j = 0; j < 4; j++) {
            int idx = tid + j * 256;
            int row = idx >> 4, seg = idx & 15;
            const void* g = srcs[m] + (size_t)row * (D_ * 2) + seg * 16;
            asm volatile("cp.async.cg.shared.global [%0], [%1], 16;"
                :: "r"(kb + offs[m] + (uint32_t)(row * 272 + seg * 16)), "l"(g));
        }
    }
    asm volatile("cp.async.commit_group;");
}

__global__ __launch_bounds__(256)
void attn_hmma(const __half* __restrict__ Qh, const __half* __restrict__ Ql,
               const __half* __restrict__ Kh, const __half* __restrict__ Kl,
               const __half* __restrict__ Vf,
               __half* __restrict__ Chi, __half* __restrict__ Clo)
{
    extern __shared__ char sm[];
    const uint32_t sb = smem_u32(sm);
    const int tid = threadIdx.x;
    const int lane = tid & 31, wid = tid >> 5;
    const int qt = (int)gridDim.x - 1 - (int)blockIdx.x;   // heavy tiles first
    const int bh = blockIdx.y;
    const int q0 = qt * 128;
    const int nt = 2 * qt + 2;

    // ---- load Q (hi+lo) as its own cp.async group ----
    {
        const __half* qsrc[2] = {Qh + ((size_t)bh * S_ + q0) * D_,
                                 Ql + ((size_t)bh * S_ + q0) * D_};
        const uint32_t qoff[2] = {AT_QH, AT_QL};
#pragma unroll
        for (int m = 0; m < 2; m++) {
#pragma unroll
            for (int j = 0; j < 8; j++) {
                int idx = tid + j * 256;
                int row = idx >> 4, seg = idx & 15;
                const void* g = qsrc[m] + (size_t)row * D_ + seg * 8;
                asm volatile("cp.async.cg.shared.global [%0], [%1], 16;"
                    :: "r"(sb + qoff[m] + (uint32_t)(row * 272 + seg * 16)), "l"(g));
            }
        }
        asm volatile("cp.async.commit_group;");
    }
    attn_issue_kv(sb, 0, bh, 0, tid, Kh, Kl, Vf);
    if (nt > 1) attn_issue_kv(sb, 1, bh, 64, tid, Kh, Kl, Vf);

    float oacc[16][4];
#pragma unroll
    for (int n = 0; n < 16; n++)
#pragma unroll
        for (int t = 0; t < 4; t++) oacc[n][t] = 0.f;
    float mrow[2] = {-1e30f, -1e30f};
    float lrow[2] = {0.f, 0.f};

    for (int kt = 0; kt < nt; kt++) {
        const int kv0 = kt * 64;
        if (kt + 1 < nt) { asm volatile("cp.async.wait_group 1;" ::: "memory"); }
        else             { asm volatile("cp.async.wait_group 0;" ::: "memory"); }
        __syncthreads();
        const uint32_t kb = sb + AT_KV0 + (uint32_t)((kt & 1) * KV_STRIDE);

        // ---- scores: S = Qh*Kh^T + Qh*Kl^T + Ql*Kh^T (fp16, pairs, dist-4) ----
        float sacc[8][4];
#pragma unroll
        for (int j = 0; j < 8; j++)
#pragma unroll
            for (int t = 0; t < 4; t++) sacc[j][t] = 0.f;

#pragma unroll
        for (int ks = 0; ks < 8; ks++) {
            uint32_t qa_h[4], qa_l[4];
            {
                int row = wid * 16 + (lane & 7) + (lane & 8);
                int seg = ks * 2 + (lane >> 4);
                ldmx4(qa_h, sb + AT_QH + (uint32_t)(row * 272 + seg * 16));
                ldmx4(qa_l, sb + AT_QL + (uint32_t)(row * 272 + seg * 16));
            }
#pragma unroll
            for (int nbp = 0; nbp < 2; nbp++) {
                int segk = ks * 2 + ((lane >> 3) & 1);
                int rowk0 = (2*nbp)   * 16 + (lane & 7) + ((lane >> 4) << 3);
                int rowk1 = (2*nbp+1) * 16 + (lane & 7) + ((lane >> 4) << 3);
                uint32_t kh0[4], kl0[4], kh1[4], kl1[4];
                ldmx4(kh0, kb + AT_KH + (uint32_t)(rowk0 * 272 + segk * 16));
                ldmx4(kh1, kb + AT_KH + (uint32_t)(rowk1 * 272 + segk * 16));
                ldmx4(kl0, kb + AT_KL + (uint32_t)(rowk0 * 272 + segk * 16));
                ldmx4(kl1, kb + AT_KL + (uint32_t)(rowk1 * 272 + segk * 16));
                float* s0 = sacc[4*nbp];     float* s1 = sacc[4*nbp+1];
                float* s2 = sacc[4*nbp+2];   float* s3 = sacc[4*nbp+3];
                mma16816f(s0, qa_h, kh0[0], kh0[1]);
                mma16816f(s1, qa_h, kh0[2], kh0[3]);
                mma16816f(s2, qa_h, kh1[0], kh1[1]);
                mma16816f(s3, qa_h, kh1[2], kh1[3]);
                mma16816f(s0, qa_l, kh0[0], kh0[1]);
                mma16816f(s1, qa_l, kh0[2], kh0[3]);
                mma16816f(s2, qa_l, kh1[0], kh1[1]);
                mma16816f(s3, qa_l, kh1[2], kh1[3]);
                mma16816f(s0, qa_h, kl0[0], kl0[1]);
                mma16816f(s1, qa_h, kl0[2], kl0[3]);
                mma16816f(s2, qa_h, kl1[0], kl1[1]);
                mma16816f(s3, qa_h, kl1[2], kl1[3]);
            }
        }

        // ---- causal mask (only last two tiles can cross the diagonal) ----
        if (kt >= nt - 2) {
#pragma unroll
            for (int j = 0; j < 8; j++)
#pragma unroll
                for (int e = 0; e < 4; e++) {
                    int col = kv0 + j * 8 + 2 * (lane & 3) + (e & 1);
                    int row = q0 + wid * 16 + (lane >> 2) + 8 * (e >> 1);
                    if (col > row) sacc[j][e] = -1e30f;
                }
        }

        // ---- online softmax (base-2; log2e folded into Q scale) ----
        float alph[2];
#pragma unroll
        for (int half = 0; half < 2; half++) {
            float mx = -1e30f;
#pragma unroll
            for (int j = 0; j < 8; j++)
                mx = fmaxf(mx, fmaxf(sacc[j][2*half], sacc[j][2*half+1]));
            mx = fmaxf(mx, __shfl_xor_sync(0xffffffffu, mx, 1));
            mx = fmaxf(mx, __shfl_xor_sync(0xffffffffu, mx, 2));
            float mo = mrow[half];
            float mn = fmaxf(mo, mx);
            float al = fexp2(mo - mn);
            float sum = 0.f;
#pragma unroll
            for (int j = 0; j < 8; j++) {
                float p0 = fexp2(sacc[j][2*half]   - mn);
                float p1 = fexp2(sacc[j][2*half+1] - mn);
                sacc[j][2*half] = p0; sacc[j][2*half+1] = p1;
                sum += p0 + p1;
            }
            sum += __shfl_xor_sync(0xffffffffu, sum, 1);
            sum += __shfl_xor_sync(0xffffffffu, sum, 2);
            mrow[half] = mn;
            lrow[half] = lrow[half] * al + sum;
            alph[half] = al;
        }
#pragma unroll
        for (int n = 0; n < 16; n++) {
            oacc[n][0] *= alph[0]; oacc[n][1] *= alph[0];
            oacc[n][2] *= alph[1]; oacc[n][3] *= alph[1];
        }

        // ---- PV (fp16): O += Ph*V + Pl*V, P split hi/lo in fp16 ----
#pragma unroll
        for (int kk = 0; kk < 4; kk++) {
            uint32_t pah[4], pal[4];
#pragma unroll
            for (int r = 0; r < 4; r++) {
                int jj = 2*kk + (r >> 1);
                float a0 = sacc[jj][(r & 1) * 2 + 0];
                float a1 = sacc[jj][(r & 1) * 2 + 1];
                uint32_t hp = pack_f16x2(a0, a1);
                union { uint32_t u; __half2 h; } cv; cv.u = hp;
                float h0f = __half2float(cv.h.x);
                float h1f = __half2float(cv.h.y);
                pah[r] = hp;
                pal[r] = pack_f16x2(a0 - h0f, a1 - h1f);
            }
            int rowv = kk * 16 + ((lane >> 3) & 1) * 8 + (lane & 7);
            int colb = (lane >> 4) * 8;
#pragma unroll
            for (int nnp = 0; nnp < 4; nnp++) {
                uint32_t va0 = (uint32_t)(rowv * 272 + ((2*nnp)   * 16 + colb) * 2);
                uint32_t va1 = (uint32_t)(rowv * 272 + ((2*nnp+1) * 16 + colb) * 2);
                uint32_t v0f[4], v1f[4];
                ldmx4t(v0f, kb + AT_V + va0);
                ldmx4t(v1f, kb + AT_V + va1);
                float* o0 = oacc[4*nnp];     float* o1 = oacc[4*nnp+1];
                float* o2 = oacc[4*nnp+2];   float* o3 = oacc[4*nnp+3];
                mma16816f(o0, pah, v0f[0], v0f[1]);
                mma16816f(o1, pah, v0f[2], v0f[3]);
                mma16816f(o2, pah, v1f[0], v1f[1]);
                mma16816f(o3, pah, v1f[2], v1f[3]);
                mma16816f(o0, pal, v0f[0], v0f[1]);
                mma16816f(o1, pal, v0f[2], v0f[3]);
                mma16816f(o2, pal, v1f[0], v1f[1]);
                mma16816f(o3, pal, v1f[2], v1f[3]);
            }
        }

        __syncthreads();
        if (kt + 2 < nt) attn_issue_kv(sb, kt & 1, bh, (kt + 2) * 64, tid, Kh, Kl, Vf);
    }

    // ---- epilogue: ctx = O / l, write fp16 hi/lo at [b*S+s][h*D+d] ----
    const int b = bh >> 4, h = bh & 15;
#pragma unroll
    for (int half = 0; half < 2; half++) {
        float inv = 1.0f / lrow[half];
        int s = q0 + wid * 16 + (lane >> 2) + 8 * half;
        size_t base = ((size_t)b * S_ + s) * (size_t)E_ + h * D_;
#pragma unroll
        for (int nn = 0; nn < 16; nn++) {
            int c = nn * 8 + 2 * (lane & 3);
            float v0 = oacc[nn][2*half]   * inv;
            float v1 = oacc[nn][2*half+1] * inv;
            __half h0 = __float2half_rn(v0);
            __half h1 = __float2half_rn(v1);
            __half l0 = __float2half_rn(v0 - __half2float(h0));
            __half l1 = __float2half_rn(v1 - __half2float(h1));
            *(__half2*)(Chi + base + c) = __halves2half2(h0, h1);
            *(__half2*)(Clo + base + c) = __halves2half2(l0, l1);
        }
    }
}

// ---------------------------------------------------------------------------
extern "C" void kernel_launch(void* const* d_in, const int* in_sizes, int n_in,
                              void* d_out, int out_size)
{
    const float* q  = (const float*)d_in[0];
    const float* k  = (const float*)d_in[1];
    const float* v  = (const float*)d_in[2];
    const float* Wq = (const float*)d_in[4];
    const float* Wk = (const float*)d_in[5];
    const float* Wv = (const float*)d_in[6];
    const float* Wo = (const float*)d_in[7];
    float* out = (float*)d_out;

    __half *qfh,*qfl,*kfh,*kfl,*vfh,*vfl;
    __half *wqf,*wkf,*wvf,*wof,*chf,*clf;
    __half *Qph,*Qpl,*Kph,*Kpl,*Vpf;
    cudaGetSymbolAddress((void**)&qfh, g_qfh); cudaGetSymbolAddress((void**)&qfl, g_qfl);
    cudaGetSymbolAddress((void**)&kfh, g_kfh); cudaGetSymbolAddress((void**)&kfl, g_kfl);
    cudaGetSymbolAddress((void**)&vfh, g_vfh); cudaGetSymbolAddress((void**)&vfl, g_vfl);
    cudaGetSymbolAddress((void**)&wqf, g_wqf); cudaGetSymbolAddress((void**)&wkf, g_wkf);
    cudaGetSymbolAddress((void**)&wvf, g_wvf); cudaGetSymbolAddress((void**)&wof, g_wof);
    cudaGetSymbolAddress((void**)&chf, g_chf); cudaGetSymbolAddress((void**)&clf, g_clf);
    cudaGetSymbolAddress((void**)&Qph, g_Qh);  cudaGetSymbolAddress((void**)&Qpl, g_Ql);
    cudaGetSymbolAddress((void**)&Kph, g_Kh);  cudaGetSymbolAddress((void**)&Kpl, g_Kl);
    cudaGetSymbolAddress((void**)&Vpf, g_Vf);

    cudaFuncSetAttribute(gemm_f16, cudaFuncAttributeMaxDynamicSharedMemorySize, GEMM_SMEM);
    cudaFuncSetAttribute(attn_hmma, cudaFuncAttributeMaxDynamicSharedMemorySize, ATTN_SMEM);

    const int nx4 = M_ * K_ / 4;
    const int nw4 = N_ * K_ / 4;

    split3_f16<<<dim3(nx4/256, 3), 256>>>(q, qfh, qfl, k, kfh, kfl, v, vfh, vfl, nx4);
    conv4_f16<<<dim3(nw4/256, 4), 256>>>(Wq, wqf, Wk, wkf, Wv, wvf, Wo, wof, nw4);

    // scale = log2(e)/sqrt(D): softmax computed base-2 is then exactly softmax(s)
    const float qscale = 0.12751744154070513f;
    dim3 gg(N_/128, M_/128);   // (16, 32)

    gemm_f16<<<gg, 128, GEMM_SMEM>>>(qfh, qfl, wqf, nullptr, Qph, Qpl, nullptr, 1, qscale);
    gemm_f16<<<gg, 128, GEMM_SMEM>>>(kfh, kfl, wkf, nullptr, Kph, Kpl, nullptr, 1, 1.0f);
    gemm_f16<<<gg, 128, GEMM_SMEM>>>(vfh, vfl, wvf, nullptr, nullptr, nullptr, Vpf, 2, 1.0f);

    attn_hmma<<<dim3(S_/128, B_*H_), 256, ATTN_SMEM>>>(Qph, Qpl, Kph, Kpl, Vpf, chf, clf);

    gemm_f16<<<gg, 128, GEMM_SMEM>>>(chf, clf, wof, out, nullptr, nullptr, nullptr, 0, 1.0f);
}

// round 17
// speedup vs baseline: 1.7393x; 1.1125x over previous
#include <cuda_runtime.h>
#include <cuda_fp16.h>
#include <math.h>
#include <cstdint>

static constexpr int B_ = 2, S_ = 2048, E_ = 2048, H_ = 16, D_ = 128;
static constexpr int M_ = B_ * S_;   // 4096
static constexpr int N_ = E_;        // 2048
static constexpr int K_ = E_;        // 2048

// ---------------- scratch (__device__ globals: allocation-free rule) --------
__device__ __half g_qfh[M_*K_], g_qfl[M_*K_];
__device__ __half g_kfh[M_*K_], g_kfl[M_*K_];
__device__ __half g_vf[M_*K_];                        // v single fp16
__device__ __half g_wqf[N_*K_], g_wkf[N_*K_], g_wvf[N_*K_], g_wof[N_*K_];
__device__ __half g_chf[M_*E_], g_clf[M_*E_];
// projections, head-split [B][H][S][D], fp16
__device__ __half g_Qh[B_*H_*S_*D_], g_Ql[B_*H_*S_*D_];
__device__ __half g_Kh[B_*H_*S_*D_], g_Kl[B_*H_*S_*D_];
__device__ __half g_Vf[B_*H_*S_*D_];

// ---------------- helpers ---------------------------------------------------
__device__ __forceinline__ uint32_t smem_u32(const void* p) {
    uint32_t a;
    asm("{ .reg .u64 t; cvta.to.shared.u64 t, %1; cvt.u32.u64 %0, t; }" : "=r"(a) : "l"(p));
    return a;
}
__device__ __forceinline__ void ldmx4(uint32_t* r, uint32_t addr) {
    asm volatile("ldmatrix.sync.aligned.m8n8.x4.shared.b16 {%0,%1,%2,%3}, [%4];"
        : "=r"(r[0]), "=r"(r[1]), "=r"(r[2]), "=r"(r[3]) : "r"(addr));
}
__device__ __forceinline__ void ldmx4t(uint32_t* r, uint32_t addr) {
    asm volatile("ldmatrix.sync.aligned.m8n8.x4.trans.shared.b16 {%0,%1,%2,%3}, [%4];"
        : "=r"(r[0]), "=r"(r[1]), "=r"(r[2]), "=r"(r[3]) : "r"(addr));
}
__device__ __forceinline__ void mma16816f(float* c, const uint32_t* a, uint32_t b0, uint32_t b1) {
    asm volatile("mma.sync.aligned.m16n8k16.row.col.f32.f16.f16.f32 "
        "{%0,%1,%2,%3}, {%4,%5,%6,%7}, {%8,%9}, {%0,%1,%2,%3};"
        : "+f"(c[0]), "+f"(c[1]), "+f"(c[2]), "+f"(c[3])
        : "r"(a[0]), "r"(a[1]), "r"(a[2]), "r"(a[3]), "r"(b0), "r"(b1));
}
__device__ __forceinline__ uint32_t pack_f16x2(float lo, float hi) {
    uint32_t d;
    asm("cvt.rn.f16x2.f32 %0, %1, %2;" : "=r"(d) : "f"(hi), "f"(lo));
    return d;
}
// fast exp2 on the FMA pipe (no MUFU). t <= 0 expected; clamped at -80.
__device__ __forceinline__ float fexp2(float t) {
    t = fmaxf(t, -80.0f);
    float r  = __fadd_rn(t, 12582912.0f);         // 1.5*2^23 magic round
    int   i  = __float_as_int(r) - 0x4B400000;
    float rf = __fadd_rn(r, -12582912.0f);
    float f  = __fadd_rn(t, -rf);                 // f in [-0.5, 0.5]
    float p  = 0.0013333558f;
    p = fmaf(p, f, 0.0096181291f);
    p = fmaf(p, f, 0.0555041087f);
    p = fmaf(p, f, 0.2402265069f);
    p = fmaf(p, f, 0.6931471806f);
    p = fmaf(p, f, 1.0f);
    return __int_as_float(__float_as_int(p) + (i << 23));
}

// ---------------- conversion kernels ----------------------------------------
// q,k: fp16 hi/lo split
__global__ __launch_bounds__(256)
void split2_f16(const float* __restrict__ x0, __half* h0, __half* l0,
                const float* __restrict__ x1, __half* h1, __half* l1,
                int n4)
{
    int i = blockIdx.x * 256 + threadIdx.x;
    if (i >= n4) return;
    const float* x; __half *hi, *lo;
    if (blockIdx.y == 0) { x = x0; hi = h0; lo = l0; }
    else                 { x = x1; hi = h1; lo = l1; }
    float4 v = ((const float4*)x)[i];
    __half a0 = __float2half_rn(v.x);
    __half a1 = __float2half_rn(v.y);
    __half a2 = __float2half_rn(v.z);
    __half a3 = __float2half_rn(v.w);
    __half b0 = __float2half_rn(v.x - __half2float(a0));
    __half b1 = __float2half_rn(v.y - __half2float(a1));
    __half b2 = __float2half_rn(v.z - __half2float(a2));
    __half b3 = __float2half_rn(v.w - __half2float(a3));
    ((__half2*)hi)[i*2]   = __halves2half2(a0, a1);
    ((__half2*)hi)[i*2+1] = __halves2half2(a2, a3);
    ((__half2*)lo)[i*2]   = __halves2half2(b0, b1);
    ((__half2*)lo)[i*2+1] = __halves2half2(b2, b3);
}

// single fp16 conversion, up to 5 tensors per launch (v + 4 weights)
__global__ __launch_bounds__(256)
void conv5_f16(const float* __restrict__ x0, __half* y0, int n0,
               const float* __restrict__ x1, __half* y1, int n1,
               const float* __restrict__ x2, __half* y2,
               const float* __restrict__ x3, __half* y3,
               const float* __restrict__ x4, __half* y4)
{
    int i = blockIdx.x * 256 + threadIdx.x;
    const float* x; __half* y; int n;
    switch (blockIdx.y) {
        case 0: x = x0; y = y0; n = n0; break;
        case 1: x = x1; y = y1; n = n1; break;
        case 2: x = x2; y = y2; n = n1; break;
        case 3: x = x3; y = y3; n = n1; break;
        default: x = x4; y = y4; n = n1; break;
    }
    if (i >= n) return;
    float4 v = ((const float4*)x)[i];
    ((__half2*)y)[i*2]   = __floats2half2_rn(v.x, v.y);
    ((__half2*)y)[i*2+1] = __floats2half2_rn(v.z, v.w);
}

// ---------------- fp16 HMMA GEMM (npass x 64 k-iters) -----------------------
// R9 pipeline: 128x128 tile, BK=32, 128 threads (4 warps 64x64), 4-stage.
// npass=2: A hi/lo; npass=1: A single (Al unused).
// mode: 0 = fp32 row-major; 1 = fp16 hi/lo head-split (scaled); 2 = fp16 single head-split.
static constexpr int GEMM_SMEM = 4 * 16384;   // 65536

__global__ __launch_bounds__(128, 2)
void gemm_f16(const __half* __restrict__ Ah, const __half* __restrict__ Al,
              const __half* __restrict__ W,
              float* __restrict__ Cf, __half* __restrict__ Chi,
              __half* __restrict__ Clo, __half* __restrict__ Cf16,
              int npass, int mode, float scale)
{
    extern __shared__ char sm[];
    const uint32_t sbase = smem_u32(sm);
    const int tid  = threadIdx.x;
    const int lane = tid & 31, wid = tid >> 5;
    const int wm = wid & 1, wn = wid >> 1;
    const int m0 = blockIdx.y * 128;
    const int n0 = blockIdx.x * 128;

    float acc[4][8][4];
#pragma unroll
    for (int i = 0; i < 4; i++)
#pragma unroll
        for (int j = 0; j < 8; j++)
#pragma unroll
            for (int t = 0; t < 4; t++) acc[i][j][t] = 0.f;

    const int crow = tid >> 2, cseg = tid & 3;
    const int NITER = npass << 6;   // npass x 64 k-iters

#define G_ISSUE(it) do { \
        int pass_ = (it) >> 6; int kb_ = ((it) & 63) << 5; \
        const __half* Ap_ = pass_ ? Al : Ah; \
        uint32_t st_ = sbase + (uint32_t)(((it) & 3) * 16384); \
        _Pragma("unroll") \
        for (int j_ = 0; j_ < 4; j_++) { \
            int row_ = crow + j_ * 32; \
            uint32_t off_ = (uint32_t)row_ * 64u + (uint32_t)((cseg ^ ((row_ >> 1) & 3)) << 4); \
            const void* ga_ = Ap_ + (size_t)(m0 + row_) * K_ + kb_ + cseg * 8; \
            const void* gb_ = W + (size_t)(n0 + row_) * K_ + kb_ + cseg * 8; \
            asm volatile("cp.async.cg.shared.global [%0], [%1], 16;" :: "r"(st_ + off_), "l"(ga_)); \
            asm volatile("cp.async.cg.shared.global [%0], [%1], 16;" :: "r"(st_ + 8192u + off_), "l"(gb_)); \
        } \
        asm volatile("cp.async.commit_group;"); \
    } while (0)

    G_ISSUE(0); G_ISSUE(1); G_ISSUE(2);

    const int rowA0 = wm * 64 + (lane & 7) + (lane & 8);
    const int asegb = (lane >> 4);
    const int rowB0 = wn * 64 + (lane & 7) + ((lane >> 4) << 3);
    const int bsegb = (lane >> 3) & 1;

    for (int it = 0; it < NITER; it++) {
        if (it < NITER - 2)      { asm volatile("cp.async.wait_group 2;" ::: "memory"); }
        else if (it == NITER - 2){ asm volatile("cp.async.wait_group 1;" ::: "memory"); }
        else                     { asm volatile("cp.async.wait_group 0;" ::: "memory"); }
        __syncthreads();
        if (it + 3 < NITER) G_ISSUE(it + 3);

        const uint32_t ab = sbase + (uint32_t)((it & 3) * 16384);
        const uint32_t bb = ab + 8192u;

#pragma unroll
        for (int ks = 0; ks < 2; ks++) {
            uint32_t a[4][4];
#pragma unroll
            for (int mt = 0; mt < 4; mt++) {
                int row = rowA0 + mt * 16;
                int sl = ks * 2 + asegb;
                ldmx4(a[mt], ab + (uint32_t)row * 64u + (uint32_t)((sl ^ ((row >> 1) & 3)) << 4));
            }
#pragma unroll
            for (int nb = 0; nb < 4; nb++) {
                int row = rowB0 + nb * 16;
                int sl = ks * 2 + bsegb;
                uint32_t b[4];
                ldmx4(b, bb + (uint32_t)row * 64u + (uint32_t)((sl ^ ((row >> 1) & 3)) << 4));
#pragma unroll
                for (int mt = 0; mt < 4; mt++) {
                    mma16816f(acc[mt][2*nb],   a[mt], b[0], b[1]);
                    mma16816f(acc[mt][2*nb+1], a[mt], b[2], b[3]);
                }
            }
        }
    }
#undef G_ISSUE

    // epilogue
#pragma unroll
    for (int mt = 0; mt < 4; mt++) {
#pragma unroll
        for (int half = 0; half < 2; half++) {
            int m = m0 + wm * 64 + mt * 16 + (lane >> 2) + half * 8;
            if (mode == 1) {
                int b = m >> 11, s = m & (S_ - 1);
                int h = blockIdx.x;
                size_t base = (((size_t)(b * H_ + h)) * S_ + s) * (size_t)D_;
#pragma unroll
                for (int n8 = 0; n8 < 8; n8++) {
                    int c = wn * 64 + n8 * 8 + 2 * (lane & 3);
                    float v0 = acc[mt][n8][half*2]   * scale;
                    float v1 = acc[mt][n8][half*2+1] * scale;
                    __half h0 = __float2half_rn(v0);
                    __half h1 = __float2half_rn(v1);
                    __half l0 = __float2half_rn(v0 - __half2float(h0));
                    __half l1 = __float2half_rn(v1 - __half2float(h1));
                    *(__half2*)(Chi + base + c) = __halves2half2(h0, h1);
                    *(__half2*)(Clo + base + c) = __halves2half2(l0, l1);
                }
            } else if (mode == 2) {
                int b = m >> 11, s = m & (S_ - 1);
                int h = blockIdx.x;
                size_t base = (((size_t)(b * H_ + h)) * S_ + s) * (size_t)D_;
#pragma unroll
                for (int n8 = 0; n8 < 8; n8++) {
                    int c = wn * 64 + n8 * 8 + 2 * (lane & 3);
                    __half2 hv = __floats2half2_rn(acc[mt][n8][half*2],
                                                   acc[mt][n8][half*2+1]);
                    *(__half2*)(Cf16 + base + c) = hv;
                }
            } else {
#pragma unroll
                for (int n8 = 0; n8 < 8; n8++) {
                    int c = wn * 64 + n8 * 8 + 2 * (lane & 3);
                    float2 v;
                    v.x = acc[mt][n8][half*2];
                    v.y = acc[mt][n8][half*2+1];
                    *(float2*)(Cf + (size_t)m * N_ + n0 + c) = v;
                }
            }
        }
    }
}

// ---------------- HMMA flash attention (all fp16) ---------------------------
// CTA: 256 threads (8 warps, 16 q-rows each), Br=128, Bc=64, D=128.
// Scores 3-pass fp16 hi/lo; PV 1-pass (P single fp16). ctx written fp16 hi/lo.
static constexpr int AT_QH  = 0;
static constexpr int AT_QL  = 34816;
static constexpr int AT_KV0 = 69632;
static constexpr int AT_KH = 0, AT_KL = 17408, AT_V = 34816;
static constexpr int KV_STRIDE = 52224;
static constexpr int ATTN_SMEM = AT_KV0 + 2 * KV_STRIDE;   // 174080

__device__ __forceinline__ void attn_issue_kv(
    uint32_t sb, int stage, int bh, int kv0, int tid,
    const __half* Kh, const __half* Kl, const __half* Vf)
{
    uint32_t kb = sb + AT_KV0 + (uint32_t)(stage * KV_STRIDE);
    const size_t ebase = ((size_t)bh * S_ + kv0) * D_;
    const char* srcs[3] = {(const char*)(Kh + ebase), (const char*)(Kl + ebase),
                           (const char*)(Vf + ebase)};
    const uint32_t offs[3] = {AT_KH, AT_KL, AT_V};
#pragma unroll
    for (int m = 0; m < 3; m++) {
#pragma unroll
        for (int j = 0; j < 4; j++) {
            int idx = tid + j * 256;
            int row = idx >> 4, seg = idx & 15;
            const void* g = srcs[m] + (size_t)row * (D_ * 2) + seg * 16;
            asm volatile("cp.async.cg.shared.global [%0], [%1], 16;"
                :: "r"(kb + offs[m] + (uint32_t)(row * 272 + seg * 16)), "l"(g));
        }
    }
    asm volatile("cp.async.commit_group;");
}

__global__ __launch_bounds__(256)
void attn_hmma(const __half* __restrict__ Qh, const __half* __restrict__ Ql,
               const __half* __restrict__ Kh, const __half* __restrict__ Kl,
               const __half* __restrict__ Vf,
               __half* __restrict__ Chi, __half* __restrict__ Clo)
{
    extern __shared__ char sm[];
    const uint32_t sb = smem_u32(sm);
    const int tid = threadIdx.x;
    const int lane = tid & 31, wid = tid >> 5;
    const int qt = (int)gridDim.x - 1 - (int)blockIdx.x;   // heavy tiles first
    const int bh = blockIdx.y;
    const int q0 = qt * 128;
    const int nt = 2 * qt + 2;

    // ---- load Q (hi+lo) as its own cp.async group ----
    {
        const __half* qsrc[2] = {Qh + ((size_t)bh * S_ + q0) * D_,
                                 Ql + ((size_t)bh * S_ + q0) * D_};
        const uint32_t qoff[2] = {AT_QH, AT_QL};
#pragma unroll
        for (int m = 0; m < 2; m++) {
#pragma unroll
            for (int j = 0; j < 8; j++) {
                int idx = tid + j * 256;
                int row = idx >> 4, seg = idx & 15;
                const void* g = qsrc[m] + (size_t)row * D_ + seg * 8;
                asm volatile("cp.async.cg.shared.global [%0], [%1], 16;"
                    :: "r"(sb + qoff[m] + (uint32_t)(row * 272 + seg * 16)), "l"(g));
            }
        }
        asm volatile("cp.async.commit_group;");
    }
    attn_issue_kv(sb, 0, bh, 0, tid, Kh, Kl, Vf);
    if (nt > 1) attn_issue_kv(sb, 1, bh, 64, tid, Kh, Kl, Vf);

    float oacc[16][4];
#pragma unroll
    for (int n = 0; n < 16; n++)
#pragma unroll
        for (int t = 0; t < 4; t++) oacc[n][t] = 0.f;
    float mrow[2] = {-1e30f, -1e30f};
    float lrow[2] = {0.f, 0.f};

    for (int kt = 0; kt < nt; kt++) {
        const int kv0 = kt * 64;
        if (kt + 1 < nt) { asm volatile("cp.async.wait_group 1;" ::: "memory"); }
        else             { asm volatile("cp.async.wait_group 0;" ::: "memory"); }
        __syncthreads();
        const uint32_t kb = sb + AT_KV0 + (uint32_t)((kt & 1) * KV_STRIDE);

        // ---- scores: S = Qh*Kh^T + Qh*Kl^T + Ql*Kh^T (fp16, pairs, dist-4) ----
        float sacc[8][4];
#pragma unroll
        for (int j = 0; j < 8; j++)
#pragma unroll
            for (int t = 0; t < 4; t++) sacc[j][t] = 0.f;

#pragma unroll
        for (int ks = 0; ks < 8; ks++) {
            uint32_t qa_h[4], qa_l[4];
            {
                int row = wid * 16 + (lane & 7) + (lane & 8);
                int seg = ks * 2 + (lane >> 4);
                ldmx4(qa_h, sb + AT_QH + (uint32_t)(row * 272 + seg * 16));
                ldmx4(qa_l, sb + AT_QL + (uint32_t)(row * 272 + seg * 16));
            }
#pragma unroll
            for (int nbp = 0; nbp < 2; nbp++) {
                int segk = ks * 2 + ((lane >> 3) & 1);
                int rowk0 = (2*nbp)   * 16 + (lane & 7) + ((lane >> 4) << 3);
                int rowk1 = (2*nbp+1) * 16 + (lane & 7) + ((lane >> 4) << 3);
                uint32_t kh0[4], kl0[4], kh1[4], kl1[4];
                ldmx4(kh0, kb + AT_KH + (uint32_t)(rowk0 * 272 + segk * 16));
                ldmx4(kh1, kb + AT_KH + (uint32_t)(rowk1 * 272 + segk * 16));
                ldmx4(kl0, kb + AT_KL + (uint32_t)(rowk0 * 272 + segk * 16));
                ldmx4(kl1, kb + AT_KL + (uint32_t)(rowk1 * 272 + segk * 16));
                float* s0 = sacc[4*nbp];     float* s1 = sacc[4*nbp+1];
                float* s2 = sacc[4*nbp+2];   float* s3 = sacc[4*nbp+3];
                mma16816f(s0, qa_h, kh0[0], kh0[1]);
                mma16816f(s1, qa_h, kh0[2], kh0[3]);
                mma16816f(s2, qa_h, kh1[0], kh1[1]);
                mma16816f(s3, qa_h, kh1[2], kh1[3]);
                mma16816f(s0, qa_l, kh0[0], kh0[1]);
                mma16816f(s1, qa_l, kh0[2], kh0[3]);
                mma16816f(s2, qa_l, kh1[0], kh1[1]);
                mma16816f(s3, qa_l, kh1[2], kh1[3]);
                mma16816f(s0, qa_h, kl0[0], kl0[1]);
                mma16816f(s1, qa_h, kl0[2], kl0[3]);
                mma16816f(s2, qa_h, kl1[0], kl1[1]);
                mma16816f(s3, qa_h, kl1[2], kl1[3]);
            }
        }

        // ---- causal mask (only last two tiles can cross the diagonal) ----
        if (kt >= nt - 2) {
#pragma unroll
            for (int j = 0; j < 8; j++)
#pragma unroll
                for (int e = 0; e < 4; e++) {
                    int col = kv0 + j * 8 + 2 * (lane & 3) + (e & 1);
                    int row = q0 + wid * 16 + (lane >> 2) + 8 * (e >> 1);
                    if (col > row) sacc[j][e] = -1e30f;
                }
        }

        // ---- online softmax (base-2; log2e folded into Q scale) ----
        float alph[2];
#pragma unroll
        for (int half = 0; half < 2; half++) {
            float mx = -1e30f;
#pragma unroll
            for (int j = 0; j < 8; j++)
                mx = fmaxf(mx, fmaxf(sacc[j][2*half], sacc[j][2*half+1]));
            mx = fmaxf(mx, __shfl_xor_sync(0xffffffffu, mx, 1));
            mx = fmaxf(mx, __shfl_xor_sync(0xffffffffu, mx, 2));
            float mo = mrow[half];
            float mn = fmaxf(mo, mx);
            float al = fexp2(mo - mn);
            float sum = 0.f;
#pragma unroll
            for (int j = 0; j < 8; j++) {
                float p0 = fexp2(sacc[j][2*half]   - mn);
                float p1 = fexp2(sacc[j][2*half+1] - mn);
                sacc[j][2*half] = p0; sacc[j][2*half+1] = p1;
                sum += p0 + p1;
            }
            sum += __shfl_xor_sync(0xffffffffu, sum, 1);
            sum += __shfl_xor_sync(0xffffffffu, sum, 2);
            mrow[half] = mn;
            lrow[half] = lrow[half] * al + sum;
            alph[half] = al;
        }
#pragma unroll
        for (int n = 0; n < 16; n++) {
            oacc[n][0] *= alph[0]; oacc[n][1] *= alph[0];
            oacc[n][2] *= alph[1]; oacc[n][3] *= alph[1];
        }

        // ---- PV (fp16, single pass): O += P*V ----
#pragma unroll
        for (int kk = 0; kk < 4; kk++) {
            uint32_t pa[4];
#pragma unroll
            for (int r = 0; r < 4; r++) {
                int jj = 2*kk + (r >> 1);
                pa[r] = pack_f16x2(sacc[jj][(r & 1) * 2 + 0],
                                   sacc[jj][(r & 1) * 2 + 1]);
            }
            int rowv = kk * 16 + ((lane >> 3) & 1) * 8 + (lane & 7);
            int colb = (lane >> 4) * 8;
#pragma unroll
            for (int nnp = 0; nnp < 4; nnp++) {
                uint32_t va0 = (uint32_t)(rowv * 272 + ((2*nnp)   * 16 + colb) * 2);
                uint32_t va1 = (uint32_t)(rowv * 272 + ((2*nnp+1) * 16 + colb) * 2);
                uint32_t v0f[4], v1f[4];
                ldmx4t(v0f, kb + AT_V + va0);
                ldmx4t(v1f, kb + AT_V + va1);
                mma16816f(oacc[4*nnp],   pa, v0f[0], v0f[1]);
                mma16816f(oacc[4*nnp+1], pa, v0f[2], v0f[3]);
                mma16816f(oacc[4*nnp+2], pa, v1f[0], v1f[1]);
                mma16816f(oacc[4*nnp+3], pa, v1f[2], v1f[3]);
            }
        }

        __syncthreads();
        if (kt + 2 < nt) attn_issue_kv(sb, kt & 1, bh, (kt + 2) * 64, tid, Kh, Kl, Vf);
    }

    // ---- epilogue: ctx = O / l, write fp16 hi/lo at [b*S+s][h*D+d] ----
    const int b = bh >> 4, h = bh & 15;
#pragma unroll
    for (int half = 0; half < 2; half++) {
        float inv = 1.0f / lrow[half];
        int s = q0 + wid * 16 + (lane >> 2) + 8 * half;
        size_t base = ((size_t)b * S_ + s) * (size_t)E_ + h * D_;
#pragma unroll
        for (int nn = 0; nn < 16; nn++) {
            int c = nn * 8 + 2 * (lane & 3);
            float v0 = oacc[nn][2*half]   * inv;
            float v1 = oacc[nn][2*half+1] * inv;
            __half h0 = __float2half_rn(v0);
            __half h1 = __float2half_rn(v1);
            __half l0 = __float2half_rn(v0 - __half2float(h0));
            __half l1 = __float2half_rn(v1 - __half2float(h1));
            *(__half2*)(Chi + base + c) = __halves2half2(h0, h1);
            *(__half2*)(Clo + base + c) = __halves2half2(l0, l1);
        }
    }
}

// ---------------------------------------------------------------------------
extern "C" void kernel_launch(void* const* d_in, const int* in_sizes, int n_in,
                              void* d_out, int out_size)
{
    const float* q  = (const float*)d_in[0];
    const float* k  = (const float*)d_in[1];
    const float* v  = (const float*)d_in[2];
    const float* Wq = (const float*)d_in[4];
    const float* Wk = (const float*)d_in[5];
    const float* Wv = (const float*)d_in[6];
    const float* Wo = (const float*)d_in[7];
    float* out = (float*)d_out;

    __half *qfh,*qfl,*kfh,*kfl,*vf;
    __half *wqf,*wkf,*wvf,*wof,*chf,*clf;
    __half *Qph,*Qpl,*Kph,*Kpl,*Vpf;
    cudaGetSymbolAddress((void**)&qfh, g_qfh); cudaGetSymbolAddress((void**)&qfl, g_qfl);
    cudaGetSymbolAddress((void**)&kfh, g_kfh); cudaGetSymbolAddress((void**)&kfl, g_kfl);
    cudaGetSymbolAddress((void**)&vf, g_vf);
    cudaGetSymbolAddress((void**)&wqf, g_wqf); cudaGetSymbolAddress((void**)&wkf, g_wkf);
    cudaGetSymbolAddress((void**)&wvf, g_wvf); cudaGetSymbolAddress((void**)&wof, g_wof);
    cudaGetSymbolAddress((void**)&chf, g_chf); cudaGetSymbolAddress((void**)&clf, g_clf);
    cudaGetSymbolAddress((void**)&Qph, g_Qh);  cudaGetSymbolAddress((void**)&Qpl, g_Ql);
    cudaGetSymbolAddress((void**)&Kph, g_Kh);  cudaGetSymbolAddress((void**)&Kpl, g_Kl);
    cudaGetSymbolAddress((void**)&Vpf, g_Vf);

    cudaFuncSetAttribute(gemm_f16, cudaFuncAttributeMaxDynamicSharedMemorySize, GEMM_SMEM);
    cudaFuncSetAttribute(attn_hmma, cudaFuncAttributeMaxDynamicSharedMemorySize, ATTN_SMEM);

    const int nx4 = M_ * K_ / 4;
    const int nw4 = N_ * K_ / 4;

    split2_f16<<<dim3(nx4/256, 2), 256>>>(q, qfh, qfl, k, kfh, kfl, nx4);
    conv5_f16<<<dim3(nx4/256, 5), 256>>>(v, vf, nx4, Wq, wqf, nw4,
                                         Wk, wkf, Wv, wvf, Wo, wof);

    // scale = log2(e)/sqrt(D): softmax computed base-2 is then exactly softmax(s)
    const float qscale = 0.12751744154070513f;
    dim3 gg(N_/128, M_/128);   // (16, 32)

    gemm_f16<<<gg, 128, GEMM_SMEM>>>(qfh, qfl, wqf, nullptr, Qph, Qpl, nullptr, 2, 1, qscale);
    gemm_f16<<<gg, 128, GEMM_SMEM>>>(kfh, kfl, wkf, nullptr, Kph, Kpl, nullptr, 2, 1, 1.0f);
    gemm_f16<<<gg, 128, GEMM_SMEM>>>(vf, nullptr, wvf, nullptr, nullptr, nullptr, Vpf, 1, 2, 1.0f);

    attn_hmma<<<dim3(S_/128, B_*H_), 256, ATTN_SMEM>>>(Qph, Qpl, Kph, Kpl, Vpf, chf, clf);

    gemm_f16<<<gg, 128, GEMM_SMEM>>>(chf, clf, wof, out, nullptr, nullptr, nullptr, 2, 0, 1.0f);
}